// round 3
// baseline (speedup 1.0000x reference)
#include <cuda_runtime.h>
#include <cuda_bf16.h>
#include <math.h>

#define EMBED  1024
#define NHEADS 16
#define HDIM   64
#define BATCH  4
#define SEQ    2048
#define MTOT   (BATCH * SEQ)   // 8192

// Scratch (allocation-free rule: __device__ globals)
__device__ float g_Q[(size_t)MTOT * EMBED];
__device__ float g_K[(size_t)MTOT * EMBED];
__device__ float g_V[(size_t)MTOT * EMBED];
__device__ float g_O[(size_t)MTOT * EMBED];

// ---------------------------------------------------------------------------
// GEMM (NT): C[m,n] = sum_k A[m,k] * W[n,k]
// A: [M,K] row-major, W: [N,K] row-major, C: [M,N] row-major
// Requires M%128==0, N%128==0, K%16==0 (true here: 8192/1024/1024)
// ---------------------------------------------------------------------------
#define BM 128
#define BN 128
#define BKK 16

__global__ __launch_bounds__(256, 2)
void gemm_nt(const float* __restrict__ A, const float* __restrict__ W,
             float* __restrict__ C, int M, int N, int K) {
    __shared__ __align__(16) float As[BKK][BM + 4];
    __shared__ __align__(16) float Ws[BKK][BN + 4];

    const int tid = threadIdx.x;
    const int tx  = tid & 15;
    const int ty  = tid >> 4;
    const int bm  = blockIdx.y * BM;
    const int bn  = blockIdx.x * BN;

    float acc[8][8];
    #pragma unroll
    for (int i = 0; i < 8; i++)
        #pragma unroll
        for (int j = 0; j < 8; j++)
            acc[i][j] = 0.0f;

    const float* Ap = A + (size_t)bm * K;
    const float* Wp = W + (size_t)bn * K;

    for (int k0 = 0; k0 < K; k0 += BKK) {
        // Stage tiles (transposed: [k][row]) — 512 float4 over 256 threads
        #pragma unroll
        for (int it = 0; it < 2; it++) {
            int f  = tid + it * 256;
            int r  = f >> 2;
            int c4 = (f & 3) << 2;
            float4 av = *(const float4*)(Ap + (size_t)r * K + k0 + c4);
            As[c4 + 0][r] = av.x; As[c4 + 1][r] = av.y;
            As[c4 + 2][r] = av.z; As[c4 + 3][r] = av.w;
            float4 wv = *(const float4*)(Wp + (size_t)r * K + k0 + c4);
            Ws[c4 + 0][r] = wv.x; Ws[c4 + 1][r] = wv.y;
            Ws[c4 + 2][r] = wv.z; Ws[c4 + 3][r] = wv.w;
        }
        __syncthreads();

        #pragma unroll
        for (int k = 0; k < BKK; k++) {
            float ra[8], rb[8];
            *(float4*)(ra)     = *(const float4*)&As[k][ty * 8];
            *(float4*)(ra + 4) = *(const float4*)&As[k][ty * 8 + 4];
            *(float4*)(rb)     = *(const float4*)&Ws[k][tx * 8];
            *(float4*)(rb + 4) = *(const float4*)&Ws[k][tx * 8 + 4];
            #pragma unroll
            for (int i = 0; i < 8; i++)
                #pragma unroll
                for (int j = 0; j < 8; j++)
                    acc[i][j] = fmaf(ra[i], rb[j], acc[i][j]);
        }
        __syncthreads();
    }

    #pragma unroll
    for (int i = 0; i < 8; i++) {
        float* cp = C + (size_t)(bm + ty * 8 + i) * N + bn + tx * 8;
        *(float4*)(cp)     = make_float4(acc[i][0], acc[i][1], acc[i][2], acc[i][3]);
        *(float4*)(cp + 4) = make_float4(acc[i][4], acc[i][5], acc[i][6], acc[i][7]);
    }
}

// ---------------------------------------------------------------------------
// Flash-style attention, fp32. Q/K/V stored [B,T,D] with head h at cols h*64.
// One block = 64 queries of one (b,h); streams 64-key tiles, online softmax.
// Dynamic smem: Qs,Ks (d-major, transposed), Vs (k-major), Ps (k-major) each [64][68]
// ---------------------------------------------------------------------------
__global__ __launch_bounds__(256, 2)
void attn_kernel(const float* __restrict__ Q, const float* __restrict__ K,
                 const float* __restrict__ V, float* __restrict__ O) {
    extern __shared__ __align__(16) float sm[];
    float* Qs = sm;               // Qs[d][q]
    float* Ks = Qs + 64 * 68;     // Ks[d][k]
    float* Vs = Ks + 64 * 68;     // Vs[k][d]
    float* Ps = Vs + 64 * 68;     // Ps[k][q]

    const int tid = threadIdx.x;
    const int tx  = tid & 15;
    const int ty  = tid >> 4;
    const int qt  = blockIdx.x;
    const int b   = blockIdx.y >> 4;
    const int h   = blockIdx.y & 15;

    const float* Qb = Q + ((size_t)b * SEQ + (size_t)qt * 64) * EMBED + h * HDIM;
    const float* Kb = K + (size_t)b * SEQ * EMBED + h * HDIM;
    const float* Vb = V + (size_t)b * SEQ * EMBED + h * HDIM;

    // Stage Q tile transposed (stays resident all iterations)
    #pragma unroll
    for (int it = 0; it < 4; it++) {
        int f  = tid + it * 256;
        int r  = f >> 4;
        int c4 = (f & 15) << 2;
        float4 v = *(const float4*)(Qb + (size_t)r * EMBED + c4);
        Qs[(c4 + 0) * 68 + r] = v.x; Qs[(c4 + 1) * 68 + r] = v.y;
        Qs[(c4 + 2) * 68 + r] = v.z; Qs[(c4 + 3) * 68 + r] = v.w;
    }

    float m_i[4], l_i[4], o[4][4];
    #pragma unroll
    for (int i = 0; i < 4; i++) {
        m_i[i] = -INFINITY;
        l_i[i] = 0.0f;
        #pragma unroll
        for (int j = 0; j < 4; j++) o[i][j] = 0.0f;
    }

    for (int kt = 0; kt < SEQ / 64; kt++) {
        __syncthreads();  // previous PV done before K/V overwrite
        const float* Kt = Kb + (size_t)kt * 64 * EMBED;
        const float* Vt = Vb + (size_t)kt * 64 * EMBED;
        #pragma unroll
        for (int it = 0; it < 4; it++) {
            int f  = tid + it * 256;
            int r  = f >> 4;
            int c4 = (f & 15) << 2;
            float4 kv = *(const float4*)(Kt + (size_t)r * EMBED + c4);
            Ks[(c4 + 0) * 68 + r] = kv.x; Ks[(c4 + 1) * 68 + r] = kv.y;
            Ks[(c4 + 2) * 68 + r] = kv.z; Ks[(c4 + 3) * 68 + r] = kv.w;
            float4 vv = *(const float4*)(Vt + (size_t)r * EMBED + c4);
            *(float4*)&Vs[r * 68 + c4] = vv;
        }
        __syncthreads();

        // S = Q . K^T  (4x4 per thread)
        float s[4][4];
        #pragma unroll
        for (int i = 0; i < 4; i++)
            #pragma unroll
            for (int j = 0; j < 4; j++) s[i][j] = 0.0f;

        #pragma unroll
        for (int d = 0; d < 64; d++) {
            float qa[4], ka[4];
            *(float4*)qa = *(const float4*)&Qs[d * 68 + ty * 4];
            *(float4*)ka = *(const float4*)&Ks[d * 68 + tx * 4];
            #pragma unroll
            for (int i = 0; i < 4; i++)
                #pragma unroll
                for (int j = 0; j < 4; j++)
                    s[i][j] = fmaf(qa[i], ka[j], s[i][j]);
        }

        // Online softmax per row; row owned by the 16 threads sharing ty
        #pragma unroll
        for (int i = 0; i < 4; i++) {
            float tmax = -INFINITY;
            #pragma unroll
            for (int j = 0; j < 4; j++) {
                s[i][j] *= 0.125f;  // 1/sqrt(64)
                tmax = fmaxf(tmax, s[i][j]);
            }
            #pragma unroll
            for (int off = 8; off > 0; off >>= 1)
                tmax = fmaxf(tmax, __shfl_xor_sync(0xffffffffu, tmax, off));
            float mnew  = fmaxf(m_i[i], tmax);
            float alpha = __expf(m_i[i] - mnew);
            float rsum  = 0.0f;
            #pragma unroll
            for (int j = 0; j < 4; j++) {
                float p = __expf(s[i][j] - mnew);
                s[i][j] = p;
                rsum += p;
            }
            #pragma unroll
            for (int off = 8; off > 0; off >>= 1)
                rsum += __shfl_xor_sync(0xffffffffu, rsum, off);
            l_i[i] = l_i[i] * alpha + rsum;
            m_i[i] = mnew;
            #pragma unroll
            for (int j = 0; j < 4; j++) o[i][j] *= alpha;
            #pragma unroll
            for (int j = 0; j < 4; j++)
                Ps[(tx * 4 + j) * 68 + ty * 4 + i] = s[i][j];
        }
        __syncthreads();

        // O += P . V
        #pragma unroll
        for (int k = 0; k < 64; k++) {
            float pa[4], va[4];
            *(float4*)pa = *(const float4*)&Ps[k * 68 + ty * 4];
            *(float4*)va = *(const float4*)&Vs[k * 68 + tx * 4];
            #pragma unroll
            for (int i = 0; i < 4; i++)
                #pragma unroll
                for (int j = 0; j < 4; j++)
                    o[i][j] = fmaf(pa[i], va[j], o[i][j]);
        }
    }

    // Normalize and write [B,T,D] with head offset
    float* Ob = O + ((size_t)b * SEQ + (size_t)qt * 64) * EMBED + h * HDIM;
    #pragma unroll
    for (int i = 0; i < 4; i++) {
        float inv = 1.0f / l_i[i];
        float* op = Ob + (size_t)(ty * 4 + i) * EMBED + tx * 4;
        *(float4*)op = make_float4(o[i][0] * inv, o[i][1] * inv,
                                   o[i][2] * inv, o[i][3] * inv);
    }
}

// ---------------------------------------------------------------------------
extern "C" void kernel_launch(void* const* d_in, const int* in_sizes, int n_in,
                              void* d_out, int out_size) {
    const float* x  = (const float*)d_in[0];
    const float* Wq = (const float*)d_in[1];
    const float* Wk = (const float*)d_in[2];
    const float* Wv = (const float*)d_in[3];
    const float* Wo = (const float*)d_in[4];
    float* out = (float*)d_out;

    float *Qp, *Kp, *Vp, *Op;
    cudaGetSymbolAddress((void**)&Qp, g_Q);
    cudaGetSymbolAddress((void**)&Kp, g_K);
    cudaGetSymbolAddress((void**)&Vp, g_V);
    cudaGetSymbolAddress((void**)&Op, g_O);

    dim3 gg(EMBED / BN, MTOT / BM);   // (8, 64)
    gemm_nt<<<gg, 256>>>(x, Wq, Qp, MTOT, EMBED, EMBED);
    gemm_nt<<<gg, 256>>>(x, Wk, Kp, MTOT, EMBED, EMBED);
    gemm_nt<<<gg, 256>>>(x, Wv, Vp, MTOT, EMBED, EMBED);

    const int smem = 4 * 64 * 68 * (int)sizeof(float);  // 69632 B
    cudaFuncSetAttribute(attn_kernel, cudaFuncAttributeMaxDynamicSharedMemorySize, smem);
    attn_kernel<<<dim3(SEQ / 64, BATCH * NHEADS), 256, smem>>>(Qp, Kp, Vp, Op);

    gemm_nt<<<gg, 256>>>(Op, Wo, out, MTOT, EMBED, EMBED);
}

// round 5
// speedup vs baseline: 1.3880x; 1.3880x over previous
#include <cuda_runtime.h>
#include <cuda.h>
#include <cuda_bf16.h>
#include <math.h>
#include <stdint.h>

#define EMBED  1024
#define NHEADS 16
#define HDIM   64
#define BATCH  4
#define SEQ    2048
#define MTOT   (BATCH * SEQ)   // 8192

// Scratch (allocation-free rule: __device__ globals)
__device__ float g_Q[(size_t)MTOT * EMBED];
__device__ float g_K[(size_t)MTOT * EMBED];
__device__ float g_V[(size_t)MTOT * EMBED];
__device__ float g_O[(size_t)MTOT * EMBED];
__device__ float g_Xr[(size_t)MTOT * EMBED];          // x rounded to tf32
__device__ float g_Wr[(size_t)4 * EMBED * EMBED];     // Wq,Wk,Wv,Wo rounded

// ---------------------------------------------------------------------------
// Helpers (baseline PTX only — no sm_103a-suffixed features!)
// ---------------------------------------------------------------------------
__device__ __forceinline__ uint32_t smem_u32(const void* p) {
    uint32_t a;
    asm("{ .reg .u64 t; cvta.to.shared.u64 t, %1; cvt.u32.u64 %0, t; }" : "=r"(a) : "l"(p));
    return a;
}
__device__ __forceinline__ void cp_async16(uint32_t dst, const void* src) {
    asm volatile("cp.async.cg.shared.global [%0], [%1], 16;" :: "r"(dst), "l"(src) : "memory");
}
__device__ __forceinline__ void cp_commit() {
    asm volatile("cp.async.commit_group;" ::: "memory");
}
template <int N>
__device__ __forceinline__ void cp_wait() {
    asm volatile("cp.async.wait_group %0;" :: "n"(N) : "memory");
}
__device__ __forceinline__ void mma_tf32(float* d, const uint32_t* a, const uint32_t* b) {
    asm volatile(
        "mma.sync.aligned.m16n8k8.row.col.f32.tf32.tf32.f32 "
        "{%0,%1,%2,%3}, {%4,%5,%6,%7}, {%8,%9}, {%0,%1,%2,%3};"
        : "+f"(d[0]), "+f"(d[1]), "+f"(d[2]), "+f"(d[3])
        : "r"(a[0]), "r"(a[1]), "r"(a[2]), "r"(a[3]), "r"(b[0]), "r"(b[1]));
}
__device__ __forceinline__ float rn_tf32(float x) {
    float r;
    asm("cvt.rna.tf32.f32 %0, %1;" : "=f"(r) : "f"(x));
    return r;
}

// ---------------------------------------------------------------------------
// Round-to-nearest tf32 conversion (zero-mean quantization error)
// ---------------------------------------------------------------------------
__global__ void round_tf32_kernel(float* __restrict__ dst, const float* __restrict__ src, int n4) {
    int i = blockIdx.x * blockDim.x + threadIdx.x;
    if (i < n4) {
        float4 v = ((const float4*)src)[i];
        v.x = rn_tf32(v.x); v.y = rn_tf32(v.y);
        v.z = rn_tf32(v.z); v.w = rn_tf32(v.w);
        ((float4*)dst)[i] = v;
    }
}

// ---------------------------------------------------------------------------
// tf32 mma.sync GEMM (NT): C[m,n] = sum_k A[m,k] * W[n,k]
// A: [M,K] row-major, W: [N,K] row-major, C: [M,N] row-major.
// Block 128x128xBK16, 8 warps (2m x 4n) of 64x32 warp tiles.
// 2-stage cp.async double buffer. Inputs must already be tf32-rounded.
// ---------------------------------------------------------------------------
#define BKG   16
#define BKP   20          // padded row: 20 floats = 80B (16B-aligned, bank-conflict-free)

__global__ __launch_bounds__(256, 2)
void gemm_mma(const float* __restrict__ A, const float* __restrict__ W,
              float* __restrict__ C, int M, int N, int K) {
    __shared__ __align__(16) float As[2][128][BKP];
    __shared__ __align__(16) float Bs[2][128][BKP];

    const int tid  = threadIdx.x;
    const int wid  = tid >> 5;
    const int lane = tid & 31;
    const int bm   = blockIdx.y * 128;
    const int bn   = blockIdx.x * 128;

    const int wm = (wid & 1) * 64;     // warp m offset
    const int wn = (wid >> 1) * 32;    // warp n offset
    const int lrow = lane >> 2;        // 0..7
    const int lcol = lane & 3;         // 0..3

    // cp.async task mapping: 512 16B-chunks per operand per stage; thread does
    // tasks tid and tid+256. task -> row = t>>2, chunk = t&3 (4 floats).
    const int r0 = tid >> 2, c0 = (tid & 3) * 4;
    const int r1 = (tid + 256) >> 2, c1 = ((tid + 256) & 3) * 4;

    float acc[4][4][4];
    #pragma unroll
    for (int mt = 0; mt < 4; mt++)
        #pragma unroll
        for (int nt = 0; nt < 4; nt++)
            #pragma unroll
            for (int j = 0; j < 4; j++) acc[mt][nt][j] = 0.0f;

    const int NK = K / BKG;   // 64

    // issue loads for k-tile kt into buffer buf
    auto issue = [&](int kt, int buf) {
        const float* Ap = A + (size_t)(bm) * K + kt * BKG;
        const float* Wp = W + (size_t)(bn) * K + kt * BKG;
        cp_async16(smem_u32(&As[buf][r0][c0]), Ap + (size_t)r0 * K + c0);
        cp_async16(smem_u32(&As[buf][r1][c1]), Ap + (size_t)r1 * K + c1);
        cp_async16(smem_u32(&Bs[buf][r0][c0]), Wp + (size_t)r0 * K + c0);
        cp_async16(smem_u32(&Bs[buf][r1][c1]), Wp + (size_t)r1 * K + c1);
    };

    issue(0, 0);
    cp_commit();

    for (int kt = 0; kt < NK; kt++) {
        const int buf = kt & 1;
        if (kt + 1 < NK) {
            issue(kt + 1, buf ^ 1);
            cp_commit();
            cp_wait<1>();
        } else {
            cp_wait<0>();
        }
        __syncthreads();

        #pragma unroll
        for (int ks = 0; ks < 2; ks++) {   // two k8 steps per BK16
            const int kb = ks * 8;
            uint32_t afr[4][4], bfr[4][2];
            #pragma unroll
            for (int mt = 0; mt < 4; mt++) {
                const int r = wm + mt * 16 + lrow;
                afr[mt][0] = __float_as_uint(As[buf][r    ][kb + lcol]);
                afr[mt][1] = __float_as_uint(As[buf][r + 8][kb + lcol]);
                afr[mt][2] = __float_as_uint(As[buf][r    ][kb + lcol + 4]);
                afr[mt][3] = __float_as_uint(As[buf][r + 8][kb + lcol + 4]);
            }
            #pragma unroll
            for (int nt = 0; nt < 4; nt++) {
                const int n = wn + nt * 8 + lrow;
                bfr[nt][0] = __float_as_uint(Bs[buf][n][kb + lcol]);
                bfr[nt][1] = __float_as_uint(Bs[buf][n][kb + lcol + 4]);
            }
            #pragma unroll
            for (int mt = 0; mt < 4; mt++)
                #pragma unroll
                for (int nt = 0; nt < 4; nt++)
                    mma_tf32(acc[mt][nt], afr[mt], bfr[nt]);
        }
        __syncthreads();
    }

    // Epilogue: c0 at (lrow, 2*lcol), c1 +1 col, c2/c3 at row+8
    #pragma unroll
    for (int mt = 0; mt < 4; mt++) {
        #pragma unroll
        for (int nt = 0; nt < 4; nt++) {
            float* Cp = C + (size_t)(bm + wm + mt * 16 + lrow) * N + bn + wn + nt * 8 + 2 * lcol;
            *(float2*)Cp = make_float2(acc[mt][nt][0], acc[mt][nt][1]);
            *(float2*)(Cp + (size_t)8 * N) = make_float2(acc[mt][nt][2], acc[mt][nt][3]);
        }
    }
}

// ---------------------------------------------------------------------------
// Flash-style attention, fp32 (unchanged — tensor-core conversion next round)
// ---------------------------------------------------------------------------
__global__ __launch_bounds__(256, 2)
void attn_kernel(const float* __restrict__ Q, const float* __restrict__ K,
                 const float* __restrict__ V, float* __restrict__ O) {
    extern __shared__ __align__(16) float sm[];
    float* Qs = sm;
    float* Ks = Qs + 64 * 68;
    float* Vs = Ks + 64 * 68;
    float* Ps = Vs + 64 * 68;

    const int tid = threadIdx.x;
    const int tx  = tid & 15;
    const int ty  = tid >> 4;
    const int qt  = blockIdx.x;
    const int b   = blockIdx.y >> 4;
    const int h   = blockIdx.y & 15;

    const float* Qb = Q + ((size_t)b * SEQ + (size_t)qt * 64) * EMBED + h * HDIM;
    const float* Kb = K + (size_t)b * SEQ * EMBED + h * HDIM;
    const float* Vb = V + (size_t)b * SEQ * EMBED + h * HDIM;

    #pragma unroll
    for (int it = 0; it < 4; it++) {
        int f  = tid + it * 256;
        int r  = f >> 4;
        int c4 = (f & 15) << 2;
        float4 v = *(const float4*)(Qb + (size_t)r * EMBED + c4);
        Qs[(c4 + 0) * 68 + r] = v.x; Qs[(c4 + 1) * 68 + r] = v.y;
        Qs[(c4 + 2) * 68 + r] = v.z; Qs[(c4 + 3) * 68 + r] = v.w;
    }

    float m_i[4], l_i[4], o[4][4];
    #pragma unroll
    for (int i = 0; i < 4; i++) {
        m_i[i] = -INFINITY;
        l_i[i] = 0.0f;
        #pragma unroll
        for (int j = 0; j < 4; j++) o[i][j] = 0.0f;
    }

    for (int kt = 0; kt < SEQ / 64; kt++) {
        __syncthreads();
        const float* Kt = Kb + (size_t)kt * 64 * EMBED;
        const float* Vt = Vb + (size_t)kt * 64 * EMBED;
        #pragma unroll
        for (int it = 0; it < 4; it++) {
            int f  = tid + it * 256;
            int r  = f >> 4;
            int c4 = (f & 15) << 2;
            float4 kv = *(const float4*)(Kt + (size_t)r * EMBED + c4);
            Ks[(c4 + 0) * 68 + r] = kv.x; Ks[(c4 + 1) * 68 + r] = kv.y;
            Ks[(c4 + 2) * 68 + r] = kv.z; Ks[(c4 + 3) * 68 + r] = kv.w;
            float4 vv = *(const float4*)(Vt + (size_t)r * EMBED + c4);
            *(float4*)&Vs[r * 68 + c4] = vv;
        }
        __syncthreads();

        float s[4][4];
        #pragma unroll
        for (int i = 0; i < 4; i++)
            #pragma unroll
            for (int j = 0; j < 4; j++) s[i][j] = 0.0f;

        #pragma unroll
        for (int d = 0; d < 64; d++) {
            float qa[4], ka[4];
            *(float4*)qa = *(const float4*)&Qs[d * 68 + ty * 4];
            *(float4*)ka = *(const float4*)&Ks[d * 68 + tx * 4];
            #pragma unroll
            for (int i = 0; i < 4; i++)
                #pragma unroll
                for (int j = 0; j < 4; j++)
                    s[i][j] = fmaf(qa[i], ka[j], s[i][j]);
        }

        #pragma unroll
        for (int i = 0; i < 4; i++) {
            float tmax = -INFINITY;
            #pragma unroll
            for (int j = 0; j < 4; j++) {
                s[i][j] *= 0.125f;
                tmax = fmaxf(tmax, s[i][j]);
            }
            #pragma unroll
            for (int off = 8; off > 0; off >>= 1)
                tmax = fmaxf(tmax, __shfl_xor_sync(0xffffffffu, tmax, off));
            float mnew  = fmaxf(m_i[i], tmax);
            float alpha = __expf(m_i[i] - mnew);
            float rsum  = 0.0f;
            #pragma unroll
            for (int j = 0; j < 4; j++) {
                float p = __expf(s[i][j] - mnew);
                s[i][j] = p;
                rsum += p;
            }
            #pragma unroll
            for (int off = 8; off > 0; off >>= 1)
                rsum += __shfl_xor_sync(0xffffffffu, rsum, off);
            l_i[i] = l_i[i] * alpha + rsum;
            m_i[i] = mnew;
            #pragma unroll
            for (int j = 0; j < 4; j++) o[i][j] *= alpha;
            #pragma unroll
            for (int j = 0; j < 4; j++)
                Ps[(tx * 4 + j) * 68 + ty * 4 + i] = s[i][j];
        }
        __syncthreads();

        #pragma unroll
        for (int k = 0; k < 64; k++) {
            float pa[4], va[4];
            *(float4*)pa = *(const float4*)&Ps[k * 68 + ty * 4];
            *(float4*)va = *(const float4*)&Vs[k * 68 + tx * 4];
            #pragma unroll
            for (int i = 0; i < 4; i++)
                #pragma unroll
                for (int j = 0; j < 4; j++)
                    o[i][j] = fmaf(pa[i], va[j], o[i][j]);
        }
    }

    float* Ob = O + ((size_t)b * SEQ + (size_t)qt * 64) * EMBED + h * HDIM;
    #pragma unroll
    for (int i = 0; i < 4; i++) {
        float inv = 1.0f / l_i[i];
        float* op = Ob + (size_t)(ty * 4 + i) * EMBED + tx * 4;
        *(float4*)op = make_float4(o[i][0] * inv, o[i][1] * inv,
                                   o[i][2] * inv, o[i][3] * inv);
    }
}

// ---------------------------------------------------------------------------
extern "C" void kernel_launch(void* const* d_in, const int* in_sizes, int n_in,
                              void* d_out, int out_size) {
    const float* x  = (const float*)d_in[0];
    const float* Wq = (const float*)d_in[1];
    const float* Wk = (const float*)d_in[2];
    const float* Wv = (const float*)d_in[3];
    const float* Wo = (const float*)d_in[4];
    float* out = (float*)d_out;

    float *Qp, *Kp, *Vp, *Op, *Xr, *Wr;
    cudaGetSymbolAddress((void**)&Qp, g_Q);
    cudaGetSymbolAddress((void**)&Kp, g_K);
    cudaGetSymbolAddress((void**)&Vp, g_V);
    cudaGetSymbolAddress((void**)&Op, g_O);
    cudaGetSymbolAddress((void**)&Xr, g_Xr);
    cudaGetSymbolAddress((void**)&Wr, g_Wr);

    const size_t WSZ = (size_t)EMBED * EMBED;

    // Round inputs to nearest-tf32 (zero-mean quantization error)
    {
        const int xn4 = (MTOT * EMBED) / 4;
        const int wn4 = (int)(WSZ / 4);
        round_tf32_kernel<<<(xn4 + 255) / 256, 256>>>(Xr, x, xn4);
        round_tf32_kernel<<<(wn4 + 255) / 256, 256>>>(Wr + 0 * WSZ, Wq, wn4);
        round_tf32_kernel<<<(wn4 + 255) / 256, 256>>>(Wr + 1 * WSZ, Wk, wn4);
        round_tf32_kernel<<<(wn4 + 255) / 256, 256>>>(Wr + 2 * WSZ, Wv, wn4);
        round_tf32_kernel<<<(wn4 + 255) / 256, 256>>>(Wr + 3 * WSZ, Wo, wn4);
    }

    dim3 gg(EMBED / 128, MTOT / 128);   // (8, 64)
    gemm_mma<<<gg, 256>>>(Xr, Wr + 0 * WSZ, Qp, MTOT, EMBED, EMBED);
    gemm_mma<<<gg, 256>>>(Xr, Wr + 1 * WSZ, Kp, MTOT, EMBED, EMBED);
    gemm_mma<<<gg, 256>>>(Xr, Wr + 2 * WSZ, Vp, MTOT, EMBED, EMBED);

    const int attn_smem = 4 * 64 * 68 * (int)sizeof(float);  // 69632 B
    cudaFuncSetAttribute(attn_kernel, cudaFuncAttributeMaxDynamicSharedMemorySize, attn_smem);
    attn_kernel<<<dim3(SEQ / 64, BATCH * NHEADS), 256, attn_smem>>>(Qp, Kp, Vp, Op);

    // Round attention output in place, then final projection on tensor cores
    {
        const int on4 = (MTOT * EMBED) / 4;
        round_tf32_kernel<<<(on4 + 255) / 256, 256>>>(Op, Op, on4);
    }
    gemm_mma<<<gg, 256>>>(Op, Wr + 3 * WSZ, out, MTOT, EMBED, EMBED);
}

// round 10
// speedup vs baseline: 2.9478x; 2.1238x over previous
#include <cuda_runtime.h>
#include <cuda.h>
#include <cuda_bf16.h>
#include <math.h>
#include <stdint.h>

#define EMBED  1024
#define NHEADS 16
#define HDIM   64
#define BATCH  4
#define SEQ    2048
#define MTOT   (BATCH * SEQ)   // 8192

// Scratch (allocation-free rule: __device__ globals)
__device__ float g_Q[(size_t)MTOT * EMBED];
__device__ float g_K[(size_t)MTOT * EMBED];
__device__ float g_V[(size_t)MTOT * EMBED];
__device__ float g_O[(size_t)MTOT * EMBED];
__device__ float g_Xr[(size_t)MTOT * EMBED];          // x rounded to tf32
__device__ float g_Wr[(size_t)4 * EMBED * EMBED];     // Wq,Wk,Wv,Wo rounded

// ---------------------------------------------------------------------------
// Helpers (baseline PTX only — no sm_103a-suffixed features)
// ---------------------------------------------------------------------------
__device__ __forceinline__ uint32_t smem_u32(const void* p) {
    uint32_t a;
    asm("{ .reg .u64 t; cvta.to.shared.u64 t, %1; cvt.u32.u64 %0, t; }" : "=r"(a) : "l"(p));
    return a;
}
__device__ __forceinline__ void cp_async16(uint32_t dst, const void* src) {
    asm volatile("cp.async.cg.shared.global [%0], [%1], 16;" :: "r"(dst), "l"(src) : "memory");
}
__device__ __forceinline__ void cp_commit() {
    asm volatile("cp.async.commit_group;" ::: "memory");
}
template <int N>
__device__ __forceinline__ void cp_wait() {
    asm volatile("cp.async.wait_group %0;" :: "n"(N) : "memory");
}
__device__ __forceinline__ void mma_tf32(float* d, const uint32_t* a, const uint32_t* b) {
    asm volatile(
        "mma.sync.aligned.m16n8k8.row.col.f32.tf32.tf32.f32 "
        "{%0,%1,%2,%3}, {%4,%5,%6,%7}, {%8,%9}, {%0,%1,%2,%3};"
        : "+f"(d[0]), "+f"(d[1]), "+f"(d[2]), "+f"(d[3])
        : "r"(a[0]), "r"(a[1]), "r"(a[2]), "r"(a[3]), "r"(b[0]), "r"(b[1]));
}
__device__ __forceinline__ float rn_tf32(float x) {
    float r;
    asm("cvt.rna.tf32.f32 %0, %1;" : "=f"(r) : "f"(x));
    return r;
}

// ---------------------------------------------------------------------------
// Round-to-nearest tf32 conversion (zero-mean quantization error)
// ---------------------------------------------------------------------------
__global__ void round_tf32_kernel(float* __restrict__ dst, const float* __restrict__ src, int n4) {
    int i = blockIdx.x * blockDim.x + threadIdx.x;
    if (i < n4) {
        float4 v = ((const float4*)src)[i];
        v.x = rn_tf32(v.x); v.y = rn_tf32(v.y);
        v.z = rn_tf32(v.z); v.w = rn_tf32(v.w);
        ((float4*)dst)[i] = v;
    }
}

// ---------------------------------------------------------------------------
// tf32 mma.sync GEMM (NT): C[m,n] = sum_k A[m,k] * W[n,k]  (unchanged from R5)
// ---------------------------------------------------------------------------
#define BKG   16
#define BKP   20

__global__ __launch_bounds__(256, 2)
void gemm_mma(const float* __restrict__ A, const float* __restrict__ W,
              float* __restrict__ C, int M, int N, int K) {
    __shared__ __align__(16) float As[2][128][BKP];
    __shared__ __align__(16) float Bs[2][128][BKP];

    const int tid  = threadIdx.x;
    const int wid  = tid >> 5;
    const int lane = tid & 31;
    const int bm   = blockIdx.y * 128;
    const int bn   = blockIdx.x * 128;

    const int wm = (wid & 1) * 64;
    const int wn = (wid >> 1) * 32;
    const int lrow = lane >> 2;
    const int lcol = lane & 3;

    const int r0 = tid >> 2, c0 = (tid & 3) * 4;
    const int r1 = (tid + 256) >> 2, c1 = ((tid + 256) & 3) * 4;

    float acc[4][4][4];
    #pragma unroll
    for (int mt = 0; mt < 4; mt++)
        #pragma unroll
        for (int nt = 0; nt < 4; nt++)
            #pragma unroll
            for (int j = 0; j < 4; j++) acc[mt][nt][j] = 0.0f;

    const int NK = K / BKG;

    auto issue = [&](int kt, int buf) {
        const float* Ap = A + (size_t)(bm) * K + kt * BKG;
        const float* Wp = W + (size_t)(bn) * K + kt * BKG;
        cp_async16(smem_u32(&As[buf][r0][c0]), Ap + (size_t)r0 * K + c0);
        cp_async16(smem_u32(&As[buf][r1][c1]), Ap + (size_t)r1 * K + c1);
        cp_async16(smem_u32(&Bs[buf][r0][c0]), Wp + (size_t)r0 * K + c0);
        cp_async16(smem_u32(&Bs[buf][r1][c1]), Wp + (size_t)r1 * K + c1);
    };

    issue(0, 0);
    cp_commit();

    for (int kt = 0; kt < NK; kt++) {
        const int buf = kt & 1;
        if (kt + 1 < NK) {
            issue(kt + 1, buf ^ 1);
            cp_commit();
            cp_wait<1>();
        } else {
            cp_wait<0>();
        }
        __syncthreads();

        #pragma unroll
        for (int ks = 0; ks < 2; ks++) {
            const int kb = ks * 8;
            uint32_t afr[4][4], bfr[4][2];
            #pragma unroll
            for (int mt = 0; mt < 4; mt++) {
                const int r = wm + mt * 16 + lrow;
                afr[mt][0] = __float_as_uint(As[buf][r    ][kb + lcol]);
                afr[mt][1] = __float_as_uint(As[buf][r + 8][kb + lcol]);
                afr[mt][2] = __float_as_uint(As[buf][r    ][kb + lcol + 4]);
                afr[mt][3] = __float_as_uint(As[buf][r + 8][kb + lcol + 4]);
            }
            #pragma unroll
            for (int nt = 0; nt < 4; nt++) {
                const int n = wn + nt * 8 + lrow;
                bfr[nt][0] = __float_as_uint(Bs[buf][n][kb + lcol]);
                bfr[nt][1] = __float_as_uint(Bs[buf][n][kb + lcol + 4]);
            }
            #pragma unroll
            for (int mt = 0; mt < 4; mt++)
                #pragma unroll
                for (int nt = 0; nt < 4; nt++)
                    mma_tf32(acc[mt][nt], afr[mt], bfr[nt]);
        }
        __syncthreads();
    }

    #pragma unroll
    for (int mt = 0; mt < 4; mt++) {
        #pragma unroll
        for (int nt = 0; nt < 4; nt++) {
            float* Cp = C + (size_t)(bm + wm + mt * 16 + lrow) * N + bn + wn + nt * 8 + 2 * lcol;
            *(float2*)Cp = make_float2(acc[mt][nt][0], acc[mt][nt][1]);
            *(float2*)(Cp + (size_t)8 * N) = make_float2(acc[mt][nt][2], acc[mt][nt][3]);
        }
    }
}

// ---------------------------------------------------------------------------
// tf32 mma.sync flash attention.
// CTA = 128 queries of one (b,h); 8 warps x 16 queries each.
// Streams 64-key tiles: S=Q.K^T (MMA) -> online softmax (register fragments,
// 4-lane shuffles only) -> P via per-warp-private smem rows -> O += P.V (MMA,
// V staged transposed). All MMA operands RNA-rounded to tf32 at staging.
// ---------------------------------------------------------------------------
#define APAD 68   // row stride in floats: 68 mod 32 = 4 -> conflict-free frag LDS

__global__ __launch_bounds__(256, 2)
void attn_mma(const float* __restrict__ Q, const float* __restrict__ K,
              const float* __restrict__ V, float* __restrict__ O) {
    extern __shared__ __align__(16) float sm[];
    float* Qs = sm;                    // [128][APAD]  q rows, d cols
    float* Ks = Qs + 128 * APAD;       // [64][APAD]   key rows, d cols
    float* Vt = Ks + 64 * APAD;        // [64][APAD]   d rows, key cols (transposed)
    float* Ps = Vt + 64 * APAD;        // [128][APAD]  q rows, key cols (warp-private rows)

    const int tid  = threadIdx.x;
    const int wid  = tid >> 5;
    const int lane = tid & 31;
    const int lrow = lane >> 2;
    const int lcol = lane & 3;
    const int wrow = wid * 16;         // warp's query-row base within tile

    const int qt = blockIdx.x;
    const int b  = blockIdx.y >> 4;
    const int h  = blockIdx.y & 15;

    const float* Qb = Q + ((size_t)b * SEQ + (size_t)qt * 128) * EMBED + h * HDIM;
    const float* Kb = K + (size_t)b * SEQ * EMBED + h * HDIM;
    const float* Vb = V + (size_t)b * SEQ * EMBED + h * HDIM;

    // Stage Q tile [128][64], rounded (tasks: 2048 float4 over 256 threads)
    #pragma unroll
    for (int it = 0; it < 8; it++) {
        int f  = tid + it * 256;
        int r  = f >> 4;
        int c4 = (f & 15) << 2;
        float4 v = *(const float4*)(Qb + (size_t)r * EMBED + c4);
        v.x = rn_tf32(v.x); v.y = rn_tf32(v.y); v.z = rn_tf32(v.z); v.w = rn_tf32(v.w);
        *(float4*)&Qs[r * APAD + c4] = v;
    }

    float m_i[2], l_i[2];
    float oc[8][4];
    m_i[0] = m_i[1] = -INFINITY;
    l_i[0] = l_i[1] = 0.0f;
    #pragma unroll
    for (int nt = 0; nt < 8; nt++)
        #pragma unroll
        for (int j = 0; j < 4; j++) oc[nt][j] = 0.0f;

    for (int kt = 0; kt < SEQ / 64; kt++) {
        __syncthreads();   // previous PV reads of Ks/Vt done
        const float* Kt = Kb + (size_t)kt * 64 * EMBED;
        const float* Vp = Vb + (size_t)kt * 64 * EMBED;
        // Stage K [64][64] rounded; V transposed -> Vt[d][k] rounded
        #pragma unroll
        for (int it = 0; it < 4; it++) {
            int f  = tid + it * 256;
            int r  = f >> 4;          // key index 0..63
            int c4 = (f & 15) << 2;   // dim base
            float4 kv = *(const float4*)(Kt + (size_t)r * EMBED + c4);
            kv.x = rn_tf32(kv.x); kv.y = rn_tf32(kv.y);
            kv.z = rn_tf32(kv.z); kv.w = rn_tf32(kv.w);
            *(float4*)&Ks[r * APAD + c4] = kv;
            float4 vv = *(const float4*)(Vp + (size_t)r * EMBED + c4);
            Vt[(c4 + 0) * APAD + r] = rn_tf32(vv.x);
            Vt[(c4 + 1) * APAD + r] = rn_tf32(vv.y);
            Vt[(c4 + 2) * APAD + r] = rn_tf32(vv.z);
            Vt[(c4 + 3) * APAD + r] = rn_tf32(vv.w);
        }
        __syncthreads();

        // ---- S = Q . K^T : warp computes 16 x 64, 8 k-steps over d ----
        float sc[8][4];
        #pragma unroll
        for (int nt = 0; nt < 8; nt++)
            #pragma unroll
            for (int j = 0; j < 4; j++) sc[nt][j] = 0.0f;

        #pragma unroll
        for (int ks = 0; ks < 8; ks++) {
            const int kb = ks * 8;
            uint32_t a[4];
            a[0] = __float_as_uint(Qs[(wrow + lrow    ) * APAD + kb + lcol]);
            a[1] = __float_as_uint(Qs[(wrow + lrow + 8) * APAD + kb + lcol]);
            a[2] = __float_as_uint(Qs[(wrow + lrow    ) * APAD + kb + lcol + 4]);
            a[3] = __float_as_uint(Qs[(wrow + lrow + 8) * APAD + kb + lcol + 4]);
            #pragma unroll
            for (int nt = 0; nt < 8; nt++) {
                uint32_t bfr[2];
                bfr[0] = __float_as_uint(Ks[(nt * 8 + lrow) * APAD + kb + lcol]);
                bfr[1] = __float_as_uint(Ks[(nt * 8 + lrow) * APAD + kb + lcol + 4]);
                mma_tf32(sc[nt], a, bfr);
            }
        }

        // ---- online softmax; rows r0=lrow, r1=lrow+8 (4 lanes share a row) ----
        #pragma unroll
        for (int rr = 0; rr < 2; rr++) {
            const int i0 = rr * 2;
            float tmax = -INFINITY;
            #pragma unroll
            for (int nt = 0; nt < 8; nt++) {
                sc[nt][i0]     *= 0.125f;
                sc[nt][i0 + 1] *= 0.125f;
                tmax = fmaxf(tmax, fmaxf(sc[nt][i0], sc[nt][i0 + 1]));
            }
            tmax = fmaxf(tmax, __shfl_xor_sync(0xffffffffu, tmax, 1));
            tmax = fmaxf(tmax, __shfl_xor_sync(0xffffffffu, tmax, 2));
            float mnew  = fmaxf(m_i[rr], tmax);
            float alpha = __expf(m_i[rr] - mnew);
            float rsum  = 0.0f;
            #pragma unroll
            for (int nt = 0; nt < 8; nt++) {
                float p0 = __expf(sc[nt][i0]     - mnew);
                float p1 = __expf(sc[nt][i0 + 1] - mnew);
                sc[nt][i0] = p0; sc[nt][i0 + 1] = p1;
                rsum += p0 + p1;
                oc[nt][i0]     *= alpha;
                oc[nt][i0 + 1] *= alpha;
                // store P (rounded) — warp-private rows, no CTA sync needed
                *(float2*)&Ps[(wrow + lrow + rr * 8) * APAD + nt * 8 + 2 * lcol] =
                    make_float2(rn_tf32(p0), rn_tf32(p1));
            }
            rsum += __shfl_xor_sync(0xffffffffu, rsum, 1);
            rsum += __shfl_xor_sync(0xffffffffu, rsum, 2);
            l_i[rr] = l_i[rr] * alpha + rsum;
            m_i[rr] = mnew;
        }
        __syncwarp();

        // ---- O += P . V : 8 k-steps over keys, 8 n-tiles over dims ----
        #pragma unroll
        for (int ks = 0; ks < 8; ks++) {
            const int kb = ks * 8;
            uint32_t a[4];
            a[0] = __float_as_uint(Ps[(wrow + lrow    ) * APAD + kb + lcol]);
            a[1] = __float_as_uint(Ps[(wrow + lrow + 8) * APAD + kb + lcol]);
            a[2] = __float_as_uint(Ps[(wrow + lrow    ) * APAD + kb + lcol + 4]);
            a[3] = __float_as_uint(Ps[(wrow + lrow + 8) * APAD + kb + lcol + 4]);
            #pragma unroll
            for (int nt = 0; nt < 8; nt++) {
                uint32_t bfr[2];
                bfr[0] = __float_as_uint(Vt[(nt * 8 + lrow) * APAD + kb + lcol]);
                bfr[1] = __float_as_uint(Vt[(nt * 8 + lrow) * APAD + kb + lcol + 4]);
                mma_tf32(oc[nt], a, bfr);
            }
        }
    }

    // Epilogue: normalize, round to tf32 (feeds Wo GEMM), write [B,T,D]
    float* Ob = O + ((size_t)b * SEQ + (size_t)qt * 128) * EMBED + h * HDIM;
    #pragma unroll
    for (int rr = 0; rr < 2; rr++) {
        const float inv = 1.0f / l_i[rr];
        const int i0 = rr * 2;
        float* orow = Ob + (size_t)(wrow + lrow + rr * 8) * EMBED + 2 * lcol;
        #pragma unroll
        for (int nt = 0; nt < 8; nt++)
            *(float2*)(orow + nt * 8) =
                make_float2(rn_tf32(oc[nt][i0] * inv), rn_tf32(oc[nt][i0 + 1] * inv));
    }
}

// ---------------------------------------------------------------------------
extern "C" void kernel_launch(void* const* d_in, const int* in_sizes, int n_in,
                              void* d_out, int out_size) {
    const float* x  = (const float*)d_in[0];
    const float* Wq = (const float*)d_in[1];
    const float* Wk = (const float*)d_in[2];
    const float* Wv = (const float*)d_in[3];
    const float* Wo = (const float*)d_in[4];
    float* out = (float*)d_out;

    float *Qp, *Kp, *Vp, *Op, *Xr, *Wr;
    cudaGetSymbolAddress((void**)&Qp, g_Q);
    cudaGetSymbolAddress((void**)&Kp, g_K);
    cudaGetSymbolAddress((void**)&Vp, g_V);
    cudaGetSymbolAddress((void**)&Op, g_O);
    cudaGetSymbolAddress((void**)&Xr, g_Xr);
    cudaGetSymbolAddress((void**)&Wr, g_Wr);

    const size_t WSZ = (size_t)EMBED * EMBED;

    // Round inputs to nearest-tf32 (zero-mean quantization error)
    {
        const int xn4 = (MTOT * EMBED) / 4;
        const int wn4 = (int)(WSZ / 4);
        round_tf32_kernel<<<(xn4 + 255) / 256, 256>>>(Xr, x, xn4);
        round_tf32_kernel<<<(wn4 + 255) / 256, 256>>>(Wr + 0 * WSZ, Wq, wn4);
        round_tf32_kernel<<<(wn4 + 255) / 256, 256>>>(Wr + 1 * WSZ, Wk, wn4);
        round_tf32_kernel<<<(wn4 + 255) / 256, 256>>>(Wr + 2 * WSZ, Wv, wn4);
        round_tf32_kernel<<<(wn4 + 255) / 256, 256>>>(Wr + 3 * WSZ, Wo, wn4);
    }

    dim3 gg(EMBED / 128, MTOT / 128);   // (8, 64)
    gemm_mma<<<gg, 256>>>(Xr, Wr + 0 * WSZ, Qp, MTOT, EMBED, EMBED);
    gemm_mma<<<gg, 256>>>(Xr, Wr + 1 * WSZ, Kp, MTOT, EMBED, EMBED);
    gemm_mma<<<gg, 256>>>(Xr, Wr + 2 * WSZ, Vp, MTOT, EMBED, EMBED);

    const int attn_smem = (128 + 64 + 64 + 128) * APAD * (int)sizeof(float);  // 104448
    cudaFuncSetAttribute(attn_mma, cudaFuncAttributeMaxDynamicSharedMemorySize, attn_smem);
    attn_mma<<<dim3(SEQ / 128, BATCH * NHEADS), 256, attn_smem>>>(Qp, Kp, Vp, Op);

    // attn epilogue already rounded O to tf32
    gemm_mma<<<gg, 256>>>(Op, Wr + 3 * WSZ, out, MTOT, EMBED, EMBED);
}

// round 11
// speedup vs baseline: 3.1412x; 1.0656x over previous
#include <cuda_runtime.h>
#include <cuda.h>
#include <cuda_bf16.h>
#include <math.h>
#include <stdint.h>

#define EMBED  1024
#define NHEADS 16
#define HDIM   64
#define BATCH  4
#define SEQ    2048
#define MTOT   (BATCH * SEQ)   // 8192
#define QSTR   3072            // fused QKV row stride

// Scratch (allocation-free rule: __device__ globals)
__device__ float g_QKV[(size_t)MTOT * QSTR];          // fused Q|K|V, rounded
__device__ float g_O[(size_t)MTOT * EMBED];
__device__ float g_Xr[(size_t)MTOT * EMBED];          // x rounded to tf32
__device__ float g_Wr[(size_t)4 * EMBED * EMBED];     // Wq,Wk,Wv,Wo rounded (Wq|Wk|Wv = [3072][1024])

// ---------------------------------------------------------------------------
// Helpers (baseline PTX only — no sm_103a-suffixed features)
// ---------------------------------------------------------------------------
__device__ __forceinline__ uint32_t smem_u32(const void* p) {
    uint32_t a;
    asm("{ .reg .u64 t; cvta.to.shared.u64 t, %1; cvt.u32.u64 %0, t; }" : "=r"(a) : "l"(p));
    return a;
}
__device__ __forceinline__ void cp_async16(uint32_t dst, const void* src) {
    asm volatile("cp.async.cg.shared.global [%0], [%1], 16;" :: "r"(dst), "l"(src) : "memory");
}
__device__ __forceinline__ void cp_commit() {
    asm volatile("cp.async.commit_group;" ::: "memory");
}
template <int N>
__device__ __forceinline__ void cp_wait() {
    asm volatile("cp.async.wait_group %0;" :: "n"(N) : "memory");
}
__device__ __forceinline__ void mma_tf32(float* d, const uint32_t* a, const uint32_t* b) {
    asm volatile(
        "mma.sync.aligned.m16n8k8.row.col.f32.tf32.tf32.f32 "
        "{%0,%1,%2,%3}, {%4,%5,%6,%7}, {%8,%9}, {%0,%1,%2,%3};"
        : "+f"(d[0]), "+f"(d[1]), "+f"(d[2]), "+f"(d[3])
        : "r"(a[0]), "r"(a[1]), "r"(a[2]), "r"(a[3]), "r"(b[0]), "r"(b[1]));
}
__device__ __forceinline__ float rn_tf32(float x) {
    float r;
    asm("cvt.rna.tf32.f32 %0, %1;" : "=f"(r) : "f"(x));
    return r;
}

// ---------------------------------------------------------------------------
// Rounding kernels (zero-mean tf32 quantization)
// ---------------------------------------------------------------------------
__global__ void round_tf32_kernel(float* __restrict__ dst, const float* __restrict__ src, int n4) {
    int i = blockIdx.x * blockDim.x + threadIdx.x;
    if (i < n4) {
        float4 v = ((const float4*)src)[i];
        v.x = rn_tf32(v.x); v.y = rn_tf32(v.y);
        v.z = rn_tf32(v.z); v.w = rn_tf32(v.w);
        ((float4*)dst)[i] = v;
    }
}
// all 4 weights in one launch; n4each is a power of two (2^18)
__global__ void round_w4_kernel(float* __restrict__ dst,
                                const float* __restrict__ w0, const float* __restrict__ w1,
                                const float* __restrict__ w2, const float* __restrict__ w3,
                                int n4each) {
    int i = blockIdx.x * blockDim.x + threadIdx.x;
    int which = i / n4each;
    int j = i - which * n4each;
    const float* src = (which == 0) ? w0 : (which == 1) ? w1 : (which == 2) ? w2 : w3;
    float4 v = ((const float4*)src)[j];
    v.x = rn_tf32(v.x); v.y = rn_tf32(v.y);
    v.z = rn_tf32(v.z); v.w = rn_tf32(v.w);
    ((float4*)dst)[i] = v;
}

// ---------------------------------------------------------------------------
// tf32 mma.sync GEMM (NT): C[m,n] = sum_k A[m,k] * W[n,k]
// round_out=1 -> epilogue rounds C to tf32 (for tensor-core consumers)
// ---------------------------------------------------------------------------
#define BKG   16
#define BKP   20

__global__ __launch_bounds__(256, 2)
void gemm_mma(const float* __restrict__ A, const float* __restrict__ W,
              float* __restrict__ C, int M, int N, int K, int round_out) {
    __shared__ __align__(16) float As[2][128][BKP];
    __shared__ __align__(16) float Bs[2][128][BKP];

    const int tid  = threadIdx.x;
    const int wid  = tid >> 5;
    const int lane = tid & 31;
    const int bm   = blockIdx.y * 128;
    const int bn   = blockIdx.x * 128;

    const int wm = (wid & 1) * 64;
    const int wn = (wid >> 1) * 32;
    const int lrow = lane >> 2;
    const int lcol = lane & 3;

    const int r0 = tid >> 2, c0 = (tid & 3) * 4;
    const int r1 = (tid + 256) >> 2, c1 = ((tid + 256) & 3) * 4;

    float acc[4][4][4];
    #pragma unroll
    for (int mt = 0; mt < 4; mt++)
        #pragma unroll
        for (int nt = 0; nt < 4; nt++)
            #pragma unroll
            for (int j = 0; j < 4; j++) acc[mt][nt][j] = 0.0f;

    const int NK = K / BKG;

    auto issue = [&](int kt, int buf) {
        const float* Ap = A + (size_t)(bm) * K + kt * BKG;
        const float* Wp = W + (size_t)(bn) * K + kt * BKG;
        cp_async16(smem_u32(&As[buf][r0][c0]), Ap + (size_t)r0 * K + c0);
        cp_async16(smem_u32(&As[buf][r1][c1]), Ap + (size_t)r1 * K + c1);
        cp_async16(smem_u32(&Bs[buf][r0][c0]), Wp + (size_t)r0 * K + c0);
        cp_async16(smem_u32(&Bs[buf][r1][c1]), Wp + (size_t)r1 * K + c1);
    };

    issue(0, 0);
    cp_commit();

    for (int kt = 0; kt < NK; kt++) {
        const int buf = kt & 1;
        if (kt + 1 < NK) {
            issue(kt + 1, buf ^ 1);
            cp_commit();
            cp_wait<1>();
        } else {
            cp_wait<0>();
        }
        __syncthreads();

        #pragma unroll
        for (int ks = 0; ks < 2; ks++) {
            const int kb = ks * 8;
            uint32_t afr[4][4], bfr[4][2];
            #pragma unroll
            for (int mt = 0; mt < 4; mt++) {
                const int r = wm + mt * 16 + lrow;
                afr[mt][0] = __float_as_uint(As[buf][r    ][kb + lcol]);
                afr[mt][1] = __float_as_uint(As[buf][r + 8][kb + lcol]);
                afr[mt][2] = __float_as_uint(As[buf][r    ][kb + lcol + 4]);
                afr[mt][3] = __float_as_uint(As[buf][r + 8][kb + lcol + 4]);
            }
            #pragma unroll
            for (int nt = 0; nt < 4; nt++) {
                const int n = wn + nt * 8 + lrow;
                bfr[nt][0] = __float_as_uint(Bs[buf][n][kb + lcol]);
                bfr[nt][1] = __float_as_uint(Bs[buf][n][kb + lcol + 4]);
            }
            #pragma unroll
            for (int mt = 0; mt < 4; mt++)
                #pragma unroll
                for (int nt = 0; nt < 4; nt++)
                    mma_tf32(acc[mt][nt], afr[mt], bfr[nt]);
        }
        __syncthreads();
    }

    #pragma unroll
    for (int mt = 0; mt < 4; mt++) {
        #pragma unroll
        for (int nt = 0; nt < 4; nt++) {
            float v0 = acc[mt][nt][0], v1 = acc[mt][nt][1];
            float v2 = acc[mt][nt][2], v3 = acc[mt][nt][3];
            if (round_out) {
                v0 = rn_tf32(v0); v1 = rn_tf32(v1);
                v2 = rn_tf32(v2); v3 = rn_tf32(v3);
            }
            float* Cp = C + (size_t)(bm + wm + mt * 16 + lrow) * N + bn + wn + nt * 8 + 2 * lcol;
            *(float2*)Cp = make_float2(v0, v1);
            *(float2*)(Cp + (size_t)8 * N) = make_float2(v2, v3);
        }
    }
}

// ---------------------------------------------------------------------------
// tf32 mma.sync flash attention over fused QKV (row stride QSTR).
// Inputs already tf32-rounded by the GEMM epilogue -> no cvt at staging.
// K/V tiles register-prefetched: K before S-MMAs, V after P-store, committed
// to smem at next iteration top (global latency hidden behind MMA blocks).
// ---------------------------------------------------------------------------
#define APAD 68

__global__ __launch_bounds__(256, 2)
void attn_mma(const float* __restrict__ QKV, float* __restrict__ O) {
    extern __shared__ __align__(16) float sm[];
    float* Qs = sm;                    // [128][APAD]
    float* Ks = Qs + 128 * APAD;       // [64][APAD]   key rows, d cols
    float* Vt = Ks + 64 * APAD;        // [64][APAD]   d rows, key cols
    float* Ps = Vt + 64 * APAD;        // [128][APAD]  warp-private rows

    const int tid  = threadIdx.x;
    const int wid  = tid >> 5;
    const int lane = tid & 31;
    const int lrow = lane >> 2;
    const int lcol = lane & 3;
    const int wrow = wid * 16;

    const int qt = blockIdx.x;
    const int b  = blockIdx.y >> 4;
    const int h  = blockIdx.y & 15;

    const float* Qb = QKV + ((size_t)b * SEQ + (size_t)qt * 128) * QSTR + h * HDIM;
    const float* Kb = QKV + (size_t)b * SEQ * QSTR + EMBED     + h * HDIM;
    const float* Vb = QKV + (size_t)b * SEQ * QSTR + 2 * EMBED + h * HDIM;

    // staging task mapping (per thread, 4 tasks): row r=f>>4 (0..63|0..127), col c4
    const int sr[4] = { tid >> 4, (tid + 256) >> 4, (tid + 512) >> 4, (tid + 768) >> 4 };
    const int sc4   = (tid & 15) << 2;

    // Stage Q tile [128][64] (already rounded)
    #pragma unroll
    for (int it = 0; it < 8; it++) {
        int f  = tid + it * 256;
        int r  = f >> 4;
        *(float4*)&Qs[r * APAD + sc4] = *(const float4*)(Qb + (size_t)r * QSTR + sc4);
    }

    float4 kreg[4], vreg[4];
    auto pf_k = [&](int kt) {
        const float* Kt = Kb + (size_t)kt * 64 * QSTR;
        #pragma unroll
        for (int it = 0; it < 4; it++)
            kreg[it] = *(const float4*)(Kt + (size_t)sr[it] * QSTR + sc4);
    };
    auto pf_v = [&](int kt) {
        const float* Vp = Vb + (size_t)kt * 64 * QSTR;
        #pragma unroll
        for (int it = 0; it < 4; it++)
            vreg[it] = *(const float4*)(Vp + (size_t)sr[it] * QSTR + sc4);
    };

    float m_i[2], l_i[2];
    float oc[8][4];
    m_i[0] = m_i[1] = -INFINITY;
    l_i[0] = l_i[1] = 0.0f;
    #pragma unroll
    for (int nt = 0; nt < 8; nt++)
        #pragma unroll
        for (int j = 0; j < 4; j++) oc[nt][j] = 0.0f;

    pf_k(0); pf_v(0);

    for (int kt = 0; kt < SEQ / 64; kt++) {
        __syncthreads();   // previous tile's MMA reads done
        // Commit prefetched K/V to smem (V transposed)
        #pragma unroll
        for (int it = 0; it < 4; it++) {
            const int r = sr[it];
            *(float4*)&Ks[r * APAD + sc4] = kreg[it];
            Vt[(sc4 + 0) * APAD + r] = vreg[it].x;
            Vt[(sc4 + 1) * APAD + r] = vreg[it].y;
            Vt[(sc4 + 2) * APAD + r] = vreg[it].z;
            Vt[(sc4 + 3) * APAD + r] = vreg[it].w;
        }
        __syncthreads();

        const bool more = (kt + 1) < (SEQ / 64);
        if (more) pf_k(kt + 1);   // latency overlaps S-MMAs below

        // ---- S = Q . K^T ----
        float scv[8][4];
        #pragma unroll
        for (int nt = 0; nt < 8; nt++)
            #pragma unroll
            for (int j = 0; j < 4; j++) scv[nt][j] = 0.0f;

        #pragma unroll
        for (int ks = 0; ks < 8; ks++) {
            const int kb = ks * 8;
            uint32_t a[4];
            a[0] = __float_as_uint(Qs[(wrow + lrow    ) * APAD + kb + lcol]);
            a[1] = __float_as_uint(Qs[(wrow + lrow + 8) * APAD + kb + lcol]);
            a[2] = __float_as_uint(Qs[(wrow + lrow    ) * APAD + kb + lcol + 4]);
            a[3] = __float_as_uint(Qs[(wrow + lrow + 8) * APAD + kb + lcol + 4]);
            #pragma unroll
            for (int nt = 0; nt < 8; nt++) {
                uint32_t bfr[2];
                bfr[0] = __float_as_uint(Ks[(nt * 8 + lrow) * APAD + kb + lcol]);
                bfr[1] = __float_as_uint(Ks[(nt * 8 + lrow) * APAD + kb + lcol + 4]);
                mma_tf32(scv[nt], a, bfr);
            }
        }

        // ---- online softmax (rows lrow, lrow+8; 4 lanes share a row) ----
        #pragma unroll
        for (int rr = 0; rr < 2; rr++) {
            const int i0 = rr * 2;
            float tmax = -INFINITY;
            #pragma unroll
            for (int nt = 0; nt < 8; nt++) {
                scv[nt][i0]     *= 0.125f;
                scv[nt][i0 + 1] *= 0.125f;
                tmax = fmaxf(tmax, fmaxf(scv[nt][i0], scv[nt][i0 + 1]));
            }
            tmax = fmaxf(tmax, __shfl_xor_sync(0xffffffffu, tmax, 1));
            tmax = fmaxf(tmax, __shfl_xor_sync(0xffffffffu, tmax, 2));
            float mnew  = fmaxf(m_i[rr], tmax);
            float alpha = __expf(m_i[rr] - mnew);
            float rsum  = 0.0f;
            #pragma unroll
            for (int nt = 0; nt < 8; nt++) {
                float p0 = __expf(scv[nt][i0]     - mnew);
                float p1 = __expf(scv[nt][i0 + 1] - mnew);
                rsum += p0 + p1;
                oc[nt][i0]     *= alpha;
                oc[nt][i0 + 1] *= alpha;
                *(float2*)&Ps[(wrow + lrow + rr * 8) * APAD + nt * 8 + 2 * lcol] =
                    make_float2(rn_tf32(p0), rn_tf32(p1));
            }
            rsum += __shfl_xor_sync(0xffffffffu, rsum, 1);
            rsum += __shfl_xor_sync(0xffffffffu, rsum, 2);
            l_i[rr] = l_i[rr] * alpha + rsum;
            m_i[rr] = mnew;
        }
        __syncwarp();

        if (more) pf_v(kt + 1);   // latency overlaps PV-MMAs below

        // ---- O += P . V ----
        #pragma unroll
        for (int ks = 0; ks < 8; ks++) {
            const int kb = ks * 8;
            uint32_t a[4];
            a[0] = __float_as_uint(Ps[(wrow + lrow    ) * APAD + kb + lcol]);
            a[1] = __float_as_uint(Ps[(wrow + lrow + 8) * APAD + kb + lcol]);
            a[2] = __float_as_uint(Ps[(wrow + lrow    ) * APAD + kb + lcol + 4]);
            a[3] = __float_as_uint(Ps[(wrow + lrow + 8) * APAD + kb + lcol + 4]);
            #pragma unroll
            for (int nt = 0; nt < 8; nt++) {
                uint32_t bfr[2];
                bfr[0] = __float_as_uint(Vt[(nt * 8 + lrow) * APAD + kb + lcol]);
                bfr[1] = __float_as_uint(Vt[(nt * 8 + lrow) * APAD + kb + lcol + 4]);
                mma_tf32(oc[nt], a, bfr);
            }
        }
    }

    // Epilogue: normalize, round (feeds Wo GEMM), write [B,T,D]
    float* Ob = O + ((size_t)b * SEQ + (size_t)qt * 128) * EMBED + h * HDIM;
    #pragma unroll
    for (int rr = 0; rr < 2; rr++) {
        const float inv = 1.0f / l_i[rr];
        const int i0 = rr * 2;
        float* orow = Ob + (size_t)(wrow + lrow + rr * 8) * EMBED + 2 * lcol;
        #pragma unroll
        for (int nt = 0; nt < 8; nt++)
            *(float2*)(orow + nt * 8) =
                make_float2(rn_tf32(oc[nt][i0] * inv), rn_tf32(oc[nt][i0 + 1] * inv));
    }
}

// ---------------------------------------------------------------------------
extern "C" void kernel_launch(void* const* d_in, const int* in_sizes, int n_in,
                              void* d_out, int out_size) {
    const float* x  = (const float*)d_in[0];
    const float* Wq = (const float*)d_in[1];
    const float* Wk = (const float*)d_in[2];
    const float* Wv = (const float*)d_in[3];
    const float* Wo = (const float*)d_in[4];
    float* out = (float*)d_out;

    float *QKVp, *Op, *Xr, *Wr;
    cudaGetSymbolAddress((void**)&QKVp, g_QKV);
    cudaGetSymbolAddress((void**)&Op, g_O);
    cudaGetSymbolAddress((void**)&Xr, g_Xr);
    cudaGetSymbolAddress((void**)&Wr, g_Wr);

    const size_t WSZ = (size_t)EMBED * EMBED;

    // Round inputs to nearest-tf32
    {
        const int xn4 = (MTOT * EMBED) / 4;
        const int wn4 = (int)(WSZ / 4);               // 262144
        round_tf32_kernel<<<(xn4 + 255) / 256, 256>>>(Xr, x, xn4);
        round_w4_kernel<<<(4 * wn4) / 256, 256>>>(Wr, Wq, Wk, Wv, Wo, wn4);
    }

    // Fused QKV projection: [8192,1024] x [3072,1024]^T -> [8192,3072], rounded
    gemm_mma<<<dim3(QSTR / 128, MTOT / 128), 256>>>(Xr, Wr, QKVp, MTOT, QSTR, EMBED, 1);

    const int attn_smem = (128 + 64 + 64 + 128) * APAD * (int)sizeof(float);  // 104448
    cudaFuncSetAttribute(attn_mma, cudaFuncAttributeMaxDynamicSharedMemorySize, attn_smem);
    attn_mma<<<dim3(SEQ / 128, BATCH * NHEADS), 256, attn_smem>>>(QKVp, Op);

    // Final projection (attn epilogue already rounded O); output stays fp32
    gemm_mma<<<dim3(EMBED / 128, MTOT / 128), 256>>>(Op, Wr + 3 * WSZ, out, MTOT, EMBED, EMBED, 0);
}

// round 14
// speedup vs baseline: 3.4037x; 1.0836x over previous
#include <cuda_runtime.h>
#include <cuda.h>
#include <cuda_bf16.h>
#include <math.h>
#include <stdint.h>

#define EMBED  1024
#define NHEADS 16
#define HDIM   64
#define BATCH  4
#define SEQ    2048
#define MTOT   (BATCH * SEQ)   // 8192
#define QSTR   3072            // fused QKV row stride

// Scratch (allocation-free rule: __device__ globals)
__device__ float g_QKV[(size_t)MTOT * QSTR];          // fused Q|K|V, rounded
__device__ float g_O[(size_t)MTOT * EMBED];
__device__ float g_Xr[(size_t)MTOT * EMBED];          // x rounded to tf32
__device__ float g_Wr[(size_t)4 * EMBED * EMBED];     // Wq,Wk,Wv,Wo rounded

// ---------------------------------------------------------------------------
// Helpers (baseline PTX only — no sm_103a-suffixed features)
// ---------------------------------------------------------------------------
__device__ __forceinline__ uint32_t smem_u32(const void* p) {
    uint32_t a;
    asm("{ .reg .u64 t; cvta.to.shared.u64 t, %1; cvt.u32.u64 %0, t; }" : "=r"(a) : "l"(p));
    return a;
}
__device__ __forceinline__ void cp_async16(uint32_t dst, const void* src) {
    asm volatile("cp.async.cg.shared.global [%0], [%1], 16;" :: "r"(dst), "l"(src) : "memory");
}
__device__ __forceinline__ void cp_commit() {
    asm volatile("cp.async.commit_group;" ::: "memory");
}
template <int N>
__device__ __forceinline__ void cp_wait() {
    asm volatile("cp.async.wait_group %0;" :: "n"(N) : "memory");
}
__device__ __forceinline__ void mma_tf32(float* d, const uint32_t* a, const uint32_t* b) {
    asm volatile(
        "mma.sync.aligned.m16n8k8.row.col.f32.tf32.tf32.f32 "
        "{%0,%1,%2,%3}, {%4,%5,%6,%7}, {%8,%9}, {%0,%1,%2,%3};"
        : "+f"(d[0]), "+f"(d[1]), "+f"(d[2]), "+f"(d[3])
        : "r"(a[0]), "r"(a[1]), "r"(a[2]), "r"(a[3]), "r"(b[0]), "r"(b[1]));
}
// ldmatrix x4: one instruction loads a full tf32 A-fragment (or two B-fragments).
__device__ __forceinline__ void ldsm_x4(uint32_t* r, uint32_t addr) {
    asm volatile("ldmatrix.sync.aligned.m8n8.x4.shared.b16 {%0,%1,%2,%3}, [%4];"
        : "=r"(r[0]), "=r"(r[1]), "=r"(r[2]), "=r"(r[3]) : "r"(addr));
}
__device__ __forceinline__ float rn_tf32(float x) {
    float r;
    asm("cvt.rna.tf32.f32 %0, %1;" : "=f"(r) : "f"(x));
    return r;
}

// ---------------------------------------------------------------------------
// Rounding kernels (zero-mean tf32 quantization)
// ---------------------------------------------------------------------------
__global__ void round_tf32_kernel(float* __restrict__ dst, const float* __restrict__ src, int n4) {
    int i = blockIdx.x * blockDim.x + threadIdx.x;
    if (i < n4) {
        float4 v = ((const float4*)src)[i];
        v.x = rn_tf32(v.x); v.y = rn_tf32(v.y);
        v.z = rn_tf32(v.z); v.w = rn_tf32(v.w);
        ((float4*)dst)[i] = v;
    }
}
__global__ void round_w4_kernel(float* __restrict__ dst,
                                const float* __restrict__ w0, const float* __restrict__ w1,
                                const float* __restrict__ w2, const float* __restrict__ w3,
                                int n4each) {
    int i = blockIdx.x * blockDim.x + threadIdx.x;
    int which = i / n4each;
    int j = i - which * n4each;
    const float* src = (which == 0) ? w0 : (which == 1) ? w1 : (which == 2) ? w2 : w3;
    float4 v = ((const float4*)src)[j];
    v.x = rn_tf32(v.x); v.y = rn_tf32(v.y);
    v.z = rn_tf32(v.z); v.w = rn_tf32(v.w);
    ((float4*)dst)[i] = v;
}

// ---------------------------------------------------------------------------
// tf32 mma.sync GEMM (NT), ldmatrix fragment loads.
// C[m,n] = sum_k A[m,k] * W[n,k]; round_out=1 rounds C to tf32 in epilogue.
// ---------------------------------------------------------------------------
#define BKG   16
#define BKP   20
#define ABUF_B (128 * BKP * 4)   // bytes per As/Bs buffer

__global__ __launch_bounds__(256, 2)
void gemm_mma(const float* __restrict__ A, const float* __restrict__ W,
              float* __restrict__ C, int M, int N, int K, int round_out) {
    __shared__ __align__(16) float As[2][128][BKP];
    __shared__ __align__(16) float Bs[2][128][BKP];

    const int tid  = threadIdx.x;
    const int wid  = tid >> 5;
    const int lane = tid & 31;
    const int bm   = blockIdx.y * 128;
    const int bn   = blockIdx.x * 128;

    const int wm = (wid & 1) * 64;
    const int wn = (wid >> 1) * 32;
    const int lrow = lane >> 2;
    const int lcol = lane & 3;

    // ldmatrix per-lane addressing: group = lane>>3 (matrix id), tr8 = lane&7 (row)
    const int grp = lane >> 3;
    const int tr8 = lane & 7;

    const int r0 = tid >> 2, c0 = (tid & 3) * 4;
    const int r1 = (tid + 256) >> 2, c1 = ((tid + 256) & 3) * 4;

    float acc[4][4][4];
    #pragma unroll
    for (int mt = 0; mt < 4; mt++)
        #pragma unroll
        for (int nt = 0; nt < 4; nt++)
            #pragma unroll
            for (int j = 0; j < 4; j++) acc[mt][nt][j] = 0.0f;

    // A-frag base addrs (per mt): row wm+mt*16+tr8+((grp&1)<<3), col ((grp>>1)<<2)
    uint32_t a_addr[4], b_addr[2];
    #pragma unroll
    for (int mt = 0; mt < 4; mt++)
        a_addr[mt] = smem_u32(&As[0][wm + mt * 16 + tr8 + ((grp & 1) << 3)][(grp >> 1) << 2]);
    // B pair pr covers nt=2pr,2pr+1: row wn+(2pr+(grp>>1))*8+tr8, col ((grp&1)<<2)
    #pragma unroll
    for (int pr = 0; pr < 2; pr++)
        b_addr[pr] = smem_u32(&Bs[0][wn + (2 * pr + (grp >> 1)) * 8 + tr8][(grp & 1) << 2]);

    const int NK = K / BKG;

    auto issue = [&](int kt, int buf) {
        const float* Ap = A + (size_t)(bm) * K + kt * BKG;
        const float* Wp = W + (size_t)(bn) * K + kt * BKG;
        cp_async16(smem_u32(&As[buf][r0][c0]), Ap + (size_t)r0 * K + c0);
        cp_async16(smem_u32(&As[buf][r1][c1]), Ap + (size_t)r1 * K + c1);
        cp_async16(smem_u32(&Bs[buf][r0][c0]), Wp + (size_t)r0 * K + c0);
        cp_async16(smem_u32(&Bs[buf][r1][c1]), Wp + (size_t)r1 * K + c1);
    };

    issue(0, 0);
    cp_commit();

    for (int kt = 0; kt < NK; kt++) {
        const int buf = kt & 1;
        const uint32_t bo = (uint32_t)buf * ABUF_B;
        if (kt + 1 < NK) {
            issue(kt + 1, buf ^ 1);
            cp_commit();
            cp_wait<1>();
        } else {
            cp_wait<0>();
        }
        __syncthreads();

        #pragma unroll
        for (int ks = 0; ks < 2; ks++) {
            const uint32_t kb4 = ks * 32;   // 8 floats = 32 bytes
            uint32_t afr[4][4];
            #pragma unroll
            for (int mt = 0; mt < 4; mt++)
                ldsm_x4(afr[mt], a_addr[mt] + bo + kb4);
            #pragma unroll
            for (int pr = 0; pr < 2; pr++) {
                uint32_t bb[4];
                ldsm_x4(bb, b_addr[pr] + bo + kb4);
                #pragma unroll
                for (int mt = 0; mt < 4; mt++) {
                    mma_tf32(acc[mt][2 * pr],     afr[mt], bb);
                    mma_tf32(acc[mt][2 * pr + 1], afr[mt], bb + 2);
                }
            }
        }
        __syncthreads();
    }

    #pragma unroll
    for (int mt = 0; mt < 4; mt++) {
        #pragma unroll
        for (int nt = 0; nt < 4; nt++) {
            float v0 = acc[mt][nt][0], v1 = acc[mt][nt][1];
            float v2 = acc[mt][nt][2], v3 = acc[mt][nt][3];
            if (round_out) {
                v0 = rn_tf32(v0); v1 = rn_tf32(v1);
                v2 = rn_tf32(v2); v3 = rn_tf32(v3);
            }
            float* Cp = C + (size_t)(bm + wm + mt * 16 + lrow) * N + bn + wn + nt * 8 + 2 * lcol;
            *(float2*)Cp = make_float2(v0, v1);
            *(float2*)(Cp + (size_t)8 * N) = make_float2(v2, v3);
        }
    }
}

// ---------------------------------------------------------------------------
// tf32 mma.sync flash attention over fused QKV, ldmatrix fragment loads.
// ---------------------------------------------------------------------------
#define APAD 68

__global__ __launch_bounds__(256, 2)
void attn_mma(const float* __restrict__ QKV, float* __restrict__ O) {
    extern __shared__ __align__(16) float sm[];
    float* Qs = sm;                    // [128][APAD]
    float* Ks = Qs + 128 * APAD;       // [64][APAD]   key rows, d cols
    float* Vt = Ks + 64 * APAD;        // [64][APAD]   d rows, key cols
    float* Ps = Vt + 64 * APAD;        // [128][APAD]  warp-private rows

    const int tid  = threadIdx.x;
    const int wid  = tid >> 5;
    const int lane = tid & 31;
    const int lrow = lane >> 2;
    const int lcol = lane & 3;
    const int wrow = wid * 16;
    const int grp  = lane >> 3;
    const int tr8  = lane & 7;

    const int qt = blockIdx.x;
    const int b  = blockIdx.y >> 4;
    const int h  = blockIdx.y & 15;

    const float* Qb = QKV + ((size_t)b * SEQ + (size_t)qt * 128) * QSTR + h * HDIM;
    const float* Kb = QKV + (size_t)b * SEQ * QSTR + EMBED     + h * HDIM;
    const float* Vb = QKV + (size_t)b * SEQ * QSTR + 2 * EMBED + h * HDIM;

    const int sr[4] = { tid >> 4, (tid + 256) >> 4, (tid + 512) >> 4, (tid + 768) >> 4 };
    const int sc4   = (tid & 15) << 2;

    // Stage Q tile [128][64] (already rounded by GEMM epilogue)
    #pragma unroll
    for (int it = 0; it < 8; it++) {
        int f  = tid + it * 256;
        int r  = f >> 4;
        *(float4*)&Qs[r * APAD + sc4] = *(const float4*)(Qb + (size_t)r * QSTR + sc4);
    }

    // ldmatrix base addresses
    const int arow = tr8 + ((grp & 1) << 3);        // row-in-16 for A-role frags
    const int acol = (grp >> 1) << 2;               // col offset (floats)
    uint32_t qs_addr = smem_u32(&Qs[(wrow + arow) * APAD + acol]);
    uint32_t ps_addr = smem_u32(&Ps[(wrow + arow) * APAD + acol]);
    uint32_t ks_addr[4], vt_addr[4];
    #pragma unroll
    for (int pr = 0; pr < 4; pr++) {
        const int brow = (2 * pr + (grp >> 1)) * 8 + tr8;
        const int bcol = (grp & 1) << 2;
        ks_addr[pr] = smem_u32(&Ks[brow * APAD + bcol]);
        vt_addr[pr] = smem_u32(&Vt[brow * APAD + bcol]);
    }

    float4 kreg[4], vreg[4];
    auto pf_k = [&](int kt) {
        const float* Kt = Kb + (size_t)kt * 64 * QSTR;
        #pragma unroll
        for (int it = 0; it < 4; it++)
            kreg[it] = *(const float4*)(Kt + (size_t)sr[it] * QSTR + sc4);
    };
    auto pf_v = [&](int kt) {
        const float* Vp = Vb + (size_t)kt * 64 * QSTR;
        #pragma unroll
        for (int it = 0; it < 4; it++)
            vreg[it] = *(const float4*)(Vp + (size_t)sr[it] * QSTR + sc4);
    };

    float m_i[2], l_i[2];
    float oc[8][4];
    m_i[0] = m_i[1] = -INFINITY;
    l_i[0] = l_i[1] = 0.0f;
    #pragma unroll
    for (int nt = 0; nt < 8; nt++)
        #pragma unroll
        for (int j = 0; j < 4; j++) oc[nt][j] = 0.0f;

    pf_k(0); pf_v(0);

    for (int kt = 0; kt < SEQ / 64; kt++) {
        __syncthreads();
        #pragma unroll
        for (int it = 0; it < 4; it++) {
            const int r = sr[it];
            *(float4*)&Ks[r * APAD + sc4] = kreg[it];
            Vt[(sc4 + 0) * APAD + r] = vreg[it].x;
            Vt[(sc4 + 1) * APAD + r] = vreg[it].y;
            Vt[(sc4 + 2) * APAD + r] = vreg[it].z;
            Vt[(sc4 + 3) * APAD + r] = vreg[it].w;
        }
        __syncthreads();

        const bool more = (kt + 1) < (SEQ / 64);
        if (more) pf_k(kt + 1);

        // ---- S = Q . K^T ----
        float scv[8][4];
        #pragma unroll
        for (int nt = 0; nt < 8; nt++)
            #pragma unroll
            for (int j = 0; j < 4; j++) scv[nt][j] = 0.0f;

        #pragma unroll
        for (int ks = 0; ks < 8; ks++) {
            const uint32_t kb4 = ks * 32;
            uint32_t a[4];
            ldsm_x4(a, qs_addr + kb4);
            #pragma unroll
            for (int pr = 0; pr < 4; pr++) {
                uint32_t bb[4];
                ldsm_x4(bb, ks_addr[pr] + kb4);
                mma_tf32(scv[2 * pr],     a, bb);
                mma_tf32(scv[2 * pr + 1], a, bb + 2);
            }
        }

        // ---- online softmax (rows lrow, lrow+8; 4 lanes share a row) ----
        #pragma unroll
        for (int rr = 0; rr < 2; rr++) {
            const int i0 = rr * 2;
            float tmax = -INFINITY;
            #pragma unroll
            for (int nt = 0; nt < 8; nt++) {
                scv[nt][i0]     *= 0.125f;
                scv[nt][i0 + 1] *= 0.125f;
                tmax = fmaxf(tmax, fmaxf(scv[nt][i0], scv[nt][i0 + 1]));
            }
            tmax = fmaxf(tmax, __shfl_xor_sync(0xffffffffu, tmax, 1));
            tmax = fmaxf(tmax, __shfl_xor_sync(0xffffffffu, tmax, 2));
            float mnew  = fmaxf(m_i[rr], tmax);
            float alpha = __expf(m_i[rr] - mnew);
            float rsum  = 0.0f;
            #pragma unroll
            for (int nt = 0; nt < 8; nt++) {
                float p0 = __expf(scv[nt][i0]     - mnew);
                float p1 = __expf(scv[nt][i0 + 1] - mnew);
                rsum += p0 + p1;
                oc[nt][i0]     *= alpha;
                oc[nt][i0 + 1] *= alpha;
                *(float2*)&Ps[(wrow + lrow + rr * 8) * APAD + nt * 8 + 2 * lcol] =
                    make_float2(rn_tf32(p0), rn_tf32(p1));
            }
            rsum += __shfl_xor_sync(0xffffffffu, rsum, 1);
            rsum += __shfl_xor_sync(0xffffffffu, rsum, 2);
            l_i[rr] = l_i[rr] * alpha + rsum;
            m_i[rr] = mnew;
        }
        __syncwarp();

        if (more) pf_v(kt + 1);

        // ---- O += P . V ----
        #pragma unroll
        for (int ks = 0; ks < 8; ks++) {
            const uint32_t kb4 = ks * 32;
            uint32_t a[4];
            ldsm_x4(a, ps_addr + kb4);
            #pragma unroll
            for (int pr = 0; pr < 4; pr++) {
                uint32_t bb[4];
                ldsm_x4(bb, vt_addr[pr] + kb4);
                mma_tf32(oc[2 * pr],     a, bb);
                mma_tf32(oc[2 * pr + 1], a, bb + 2);
            }
        }
    }

    // Epilogue: normalize, round (feeds Wo GEMM), write [B,T,D]
    float* Ob = O + ((size_t)b * SEQ + (size_t)qt * 128) * EMBED + h * HDIM;
    #pragma unroll
    for (int rr = 0; rr < 2; rr++) {
        const float inv = 1.0f / l_i[rr];
        const int i0 = rr * 2;
        float* orow = Ob + (size_t)(wrow + lrow + rr * 8) * EMBED + 2 * lcol;
        #pragma unroll
        for (int nt = 0; nt < 8; nt++)
            *(float2*)(orow + nt * 8) =
                make_float2(rn_tf32(oc[nt][i0] * inv), rn_tf32(oc[nt][i0 + 1] * inv));
    }
}

// ---------------------------------------------------------------------------
extern "C" void kernel_launch(void* const* d_in, const int* in_sizes, int n_in,
                              void* d_out, int out_size) {
    const float* x  = (const float*)d_in[0];
    const float* Wq = (const float*)d_in[1];
    const float* Wk = (const float*)d_in[2];
    const float* Wv = (const float*)d_in[3];
    const float* Wo = (const float*)d_in[4];
    float* out = (float*)d_out;

    float *QKVp, *Op, *Xr, *Wr;
    cudaGetSymbolAddress((void**)&QKVp, g_QKV);
    cudaGetSymbolAddress((void**)&Op, g_O);
    cudaGetSymbolAddress((void**)&Xr, g_Xr);
    cudaGetSymbolAddress((void**)&Wr, g_Wr);

    const size_t WSZ = (size_t)EMBED * EMBED;

    // Round inputs to nearest-tf32
    {
        const int xn4 = (MTOT * EMBED) / 4;
        const int wn4 = (int)(WSZ / 4);
        round_tf32_kernel<<<(xn4 + 255) / 256, 256>>>(Xr, x, xn4);
        round_w4_kernel<<<(4 * wn4) / 256, 256>>>(Wr, Wq, Wk, Wv, Wo, wn4);
    }

    // Fused QKV projection: [8192,1024] x [3072,1024]^T -> [8192,3072], rounded
    gemm_mma<<<dim3(QSTR / 128, MTOT / 128), 256>>>(Xr, Wr, QKVp, MTOT, QSTR, EMBED, 1);

    const int attn_smem = (128 + 64 + 64 + 128) * APAD * (int)sizeof(float);  // 104448
    cudaFuncSetAttribute(attn_mma, cudaFuncAttributeMaxDynamicSharedMemorySize, attn_smem);
    attn_mma<<<dim3(SEQ / 128, BATCH * NHEADS), 256, attn_smem>>>(QKVp, Op);

    // Final projection (attn epilogue already rounded O); output stays fp32
    gemm_mma<<<dim3(EMBED / 128, MTOT / 128), 256>>>(Op, Wr + 3 * WSZ, out, MTOT, EMBED, EMBED, 0);
}

// round 15
// speedup vs baseline: 7.0277x; 2.0647x over previous
#include <cuda_runtime.h>
#include <cuda.h>
#include <cuda_fp16.h>
#include <math.h>
#include <stdint.h>

#define EMBED  1024
#define NHEADS 16
#define HDIM   64
#define BATCH  4
#define SEQ    2048
#define MTOT   (BATCH * SEQ)   // 8192
#define QSTR   3072            // fused QKV row stride (halves)

// Scratch (allocation-free rule: __device__ globals)
__device__ __half g_QKVh[(size_t)MTOT * QSTR];        // fused Q|K|V, fp16
__device__ __half g_Oh[(size_t)MTOT * EMBED];         // attention out, fp16
__device__ __half g_Xh[(size_t)MTOT * EMBED];         // x in fp16
__device__ __half g_Wh[(size_t)4 * EMBED * EMBED];    // Wq|Wk|Wv|Wo in fp16

// ---------------------------------------------------------------------------
// Helpers (baseline PTX only — no sm_103a-suffixed features)
// ---------------------------------------------------------------------------
__device__ __forceinline__ uint32_t smem_u32(const void* p) {
    uint32_t a;
    asm("{ .reg .u64 t; cvta.to.shared.u64 t, %1; cvt.u32.u64 %0, t; }" : "=r"(a) : "l"(p));
    return a;
}
__device__ __forceinline__ void cp_async16(uint32_t dst, const void* src) {
    asm volatile("cp.async.cg.shared.global [%0], [%1], 16;" :: "r"(dst), "l"(src) : "memory");
}
__device__ __forceinline__ void cp_commit() {
    asm volatile("cp.async.commit_group;" ::: "memory");
}
template <int N>
__device__ __forceinline__ void cp_wait() {
    asm volatile("cp.async.wait_group %0;" :: "n"(N) : "memory");
}
// fp16 MMA, fp32 accumulate: D(16x8) += A(16x16) * B(16x8)
__device__ __forceinline__ void mma_f16(float* d, const uint32_t* a, const uint32_t* b) {
    asm volatile(
        "mma.sync.aligned.m16n8k16.row.col.f32.f16.f16.f32 "
        "{%0,%1,%2,%3}, {%4,%5,%6,%7}, {%8,%9}, {%0,%1,%2,%3};"
        : "+f"(d[0]), "+f"(d[1]), "+f"(d[2]), "+f"(d[3])
        : "r"(a[0]), "r"(a[1]), "r"(a[2]), "r"(a[3]), "r"(b[0]), "r"(b[1]));
}
__device__ __forceinline__ void ldsm_x4(uint32_t* r, uint32_t addr) {
    asm volatile("ldmatrix.sync.aligned.m8n8.x4.shared.b16 {%0,%1,%2,%3}, [%4];"
        : "=r"(r[0]), "=r"(r[1]), "=r"(r[2]), "=r"(r[3]) : "r"(addr));
}
__device__ __forceinline__ void ldsm_x4_t(uint32_t* r, uint32_t addr) {
    asm volatile("ldmatrix.sync.aligned.m8n8.x4.trans.shared.b16 {%0,%1,%2,%3}, [%4];"
        : "=r"(r[0]), "=r"(r[1]), "=r"(r[2]), "=r"(r[3]) : "r"(addr));
}

// ---------------------------------------------------------------------------
// fp32 -> fp16 conversion kernels (8 floats / thread)
// ---------------------------------------------------------------------------
__global__ void f32_to_f16_kernel(__half* __restrict__ dst, const float* __restrict__ src, int n8) {
    int i = blockIdx.x * blockDim.x + threadIdx.x;
    if (i < n8) {
        const float4* s = (const float4*)src + 2 * (size_t)i;
        float4 v0 = s[0], v1 = s[1];
        __half2 h0 = __floats2half2_rn(v0.x, v0.y);
        __half2 h1 = __floats2half2_rn(v0.z, v0.w);
        __half2 h2 = __floats2half2_rn(v1.x, v1.y);
        __half2 h3 = __floats2half2_rn(v1.z, v1.w);
        uint4 o;
        o.x = *(uint32_t*)&h0; o.y = *(uint32_t*)&h1;
        o.z = *(uint32_t*)&h2; o.w = *(uint32_t*)&h3;
        ((uint4*)dst)[i] = o;
    }
}
__global__ void f32_to_f16_w4(__half* __restrict__ dst,
                              const float* __restrict__ w0, const float* __restrict__ w1,
                              const float* __restrict__ w2, const float* __restrict__ w3,
                              int n8each) {
    int i = blockIdx.x * blockDim.x + threadIdx.x;
    int which = i / n8each;
    int j = i - which * n8each;
    const float* src = (which == 0) ? w0 : (which == 1) ? w1 : (which == 2) ? w2 : w3;
    const float4* s = (const float4*)src + 2 * (size_t)j;
    float4 v0 = s[0], v1 = s[1];
    __half2 h0 = __floats2half2_rn(v0.x, v0.y);
    __half2 h1 = __floats2half2_rn(v0.z, v0.w);
    __half2 h2 = __floats2half2_rn(v1.x, v1.y);
    __half2 h3 = __floats2half2_rn(v1.z, v1.w);
    uint4 o;
    o.x = *(uint32_t*)&h0; o.y = *(uint32_t*)&h1;
    o.z = *(uint32_t*)&h2; o.w = *(uint32_t*)&h3;
    ((uint4*)dst)[i] = o;
}

// ---------------------------------------------------------------------------
// fp16 mma.sync GEMM (NT): C[m,n] = sum_k A[m,k] * W[n,k]
// A [M,K] fp16, W [N,K] fp16; C fp16 (Ch) or fp32 (Cf). fp32 accumulate.
// Block 128x128xk32, 8 warps (2m x 4n) of 64x32 warp tiles, m16n8k16.
// ---------------------------------------------------------------------------
#define GBK   32
#define GSTR  40                      // smem row stride (halves) = 80B -> conflict-free ldsm
#define GBUF_BYTES (128 * GSTR * 2)   // one buffer, one operand

__global__ __launch_bounds__(256, 2)
void gemm_h(const __half* __restrict__ A, const __half* __restrict__ W,
            float* __restrict__ Cf, __half* __restrict__ Ch, int M, int N, int K) {
    __shared__ __align__(16) __half As[2][128][GSTR];
    __shared__ __align__(16) __half Bs[2][128][GSTR];

    const int tid  = threadIdx.x;
    const int wid  = tid >> 5;
    const int lane = tid & 31;
    const int bm   = blockIdx.y * 128;
    const int bn   = blockIdx.x * 128;

    const int wm = (wid & 1) * 64;
    const int wn = (wid >> 1) * 32;
    const int lrow = lane >> 2;
    const int lcol = lane & 3;

    // cp.async task map: 512 chunks (16B = 8 halves) per operand per stage
    const int r0 = tid >> 2, c0 = (tid & 3) * 8;
    const int r1 = (tid + 256) >> 2, c1 = ((tid + 256) & 3) * 8;

    float acc[4][4][4];
    #pragma unroll
    for (int mt = 0; mt < 4; mt++)
        #pragma unroll
        for (int nt = 0; nt < 4; nt++)
            #pragma unroll
            for (int j = 0; j < 4; j++) acc[mt][nt][j] = 0.0f;

    // ldmatrix base addresses (A-role: rows lane&15, col-half (lane>>4)*8)
    uint32_t a_addr[4], b_addr[2];
    #pragma unroll
    for (int mt = 0; mt < 4; mt++)
        a_addr[mt] = smem_u32(&As[0][wm + mt * 16 + (lane & 15)][(lane >> 4) << 3]);
    // B-role from [n][k]: rows n (16 per pr), col-half lane&8
    #pragma unroll
    for (int pr = 0; pr < 2; pr++)
        b_addr[pr] = smem_u32(&Bs[0][wn + pr * 16 + ((lane >> 4) << 3) + (lane & 7)][lane & 8]);

    const int NK = K / GBK;

    auto issue = [&](int kt, int buf) {
        const __half* Ap = A + (size_t)bm * K + kt * GBK;
        const __half* Wp = W + (size_t)bn * K + kt * GBK;
        cp_async16(smem_u32(&As[buf][r0][c0]), Ap + (size_t)r0 * K + c0);
        cp_async16(smem_u32(&As[buf][r1][c1]), Ap + (size_t)r1 * K + c1);
        cp_async16(smem_u32(&Bs[buf][r0][c0]), Wp + (size_t)r0 * K + c0);
        cp_async16(smem_u32(&Bs[buf][r1][c1]), Wp + (size_t)r1 * K + c1);
    };

    issue(0, 0);
    cp_commit();

    for (int kt = 0; kt < NK; kt++) {
        const int buf = kt & 1;
        const uint32_t bo = (uint32_t)buf * GBUF_BYTES;
        if (kt + 1 < NK) {
            issue(kt + 1, buf ^ 1);
            cp_commit();
            cp_wait<1>();
        } else {
            cp_wait<0>();
        }
        __syncthreads();

        #pragma unroll
        for (int ks = 0; ks < 2; ks++) {
            const uint32_t kb = ks * 32;   // 16 halves = 32 bytes
            uint32_t af[4][4];
            #pragma unroll
            for (int mt = 0; mt < 4; mt++)
                ldsm_x4(af[mt], a_addr[mt] + bo + kb);
            #pragma unroll
            for (int pr = 0; pr < 2; pr++) {
                uint32_t bb[4];
                ldsm_x4(bb, b_addr[pr] + bo + kb);
                #pragma unroll
                for (int mt = 0; mt < 4; mt++) {
                    mma_f16(acc[mt][2 * pr],     af[mt], bb);
                    mma_f16(acc[mt][2 * pr + 1], af[mt], bb + 2);
                }
            }
        }
        __syncthreads();
    }

    // Epilogue: accumulator (lrow, 2lcol | +1), (lrow+8, ...) per nt tile
    #pragma unroll
    for (int mt = 0; mt < 4; mt++) {
        #pragma unroll
        for (int nt = 0; nt < 4; nt++) {
            const int row = bm + wm + mt * 16 + lrow;
            const int col = bn + wn + nt * 8 + 2 * lcol;
            if (Ch) {
                __half2 h0 = __floats2half2_rn(acc[mt][nt][0], acc[mt][nt][1]);
                __half2 h1 = __floats2half2_rn(acc[mt][nt][2], acc[mt][nt][3]);
                *(__half2*)(Ch + (size_t)row * N + col) = h0;
                *(__half2*)(Ch + (size_t)(row + 8) * N + col) = h1;
            } else {
                *(float2*)(Cf + (size_t)row * N + col) =
                    make_float2(acc[mt][nt][0], acc[mt][nt][1]);
                *(float2*)(Cf + (size_t)(row + 8) * N + col) =
                    make_float2(acc[mt][nt][2], acc[mt][nt][3]);
            }
        }
    }
}

// ---------------------------------------------------------------------------
// fp16 mma.sync flash attention over fused QKV.
// CTA = 128 queries of one (b,h); 8 warps x 16 query rows.
// S = Q.K^T via m16n8k16 (4 k-steps over d); online softmax fp32;
// P -> fp16 smem (warp-private rows); O += P.V with V fragments loaded by
// ldmatrix.x4.trans straight from the natural [key][d] layout (no transpose
// staging). K/V register-prefetched. fp32 accumulators throughout.
// ---------------------------------------------------------------------------
#define ASTR 72   // smem row stride (halves) = 144B -> conflict-free ldsm

__global__ __launch_bounds__(256, 2)
void attn_h(const __half* __restrict__ QKV, __half* __restrict__ O) {
    extern __shared__ __align__(16) __half smh[];
    __half* Qs = smh;                  // [128][ASTR]  q rows, d cols
    __half* Ks = Qs + 128 * ASTR;      // [64][ASTR]   key rows, d cols
    __half* Vs = Ks + 64 * ASTR;       // [64][ASTR]   key rows, d cols (natural!)
    __half* Ps = Vs + 64 * ASTR;       // [128][ASTR]  q rows, key cols

    const int tid  = threadIdx.x;
    const int wid  = tid >> 5;
    const int lane = tid & 31;
    const int lrow = lane >> 2;
    const int lcol = lane & 3;
    const int wrow = wid * 16;

    const int qt = blockIdx.x;
    const int b  = blockIdx.y >> 4;
    const int h  = blockIdx.y & 15;

    const __half* Qb = QKV + ((size_t)b * SEQ + (size_t)qt * 128) * QSTR + h * HDIM;
    const __half* Kb = QKV + (size_t)b * SEQ * QSTR + EMBED     + h * HDIM;
    const __half* Vb = QKV + (size_t)b * SEQ * QSTR + 2 * EMBED + h * HDIM;

    // Staging task map: chunk f -> row f>>3, col (f&7)*8 halves (16B)
    const int sc8 = (tid & 7) * 8;

    // Stage Q tile [128][64]
    #pragma unroll
    for (int it = 0; it < 4; it++) {
        int f = tid + it * 256;
        int r = f >> 3;
        int c = (f & 7) * 8;
        *(uint4*)&Qs[r * ASTR + c] = *(const uint4*)(Qb + (size_t)r * QSTR + c);
    }

    // ldmatrix base addresses
    uint32_t qs_addr = smem_u32(&Qs[(wrow + (lane & 15)) * ASTR + ((lane >> 4) << 3)]);
    uint32_t ps_addr = smem_u32(&Ps[(wrow + (lane & 15)) * ASTR + ((lane >> 4) << 3)]);
    uint32_t ks_addr[4], vs_addr[4];
    #pragma unroll
    for (int pr = 0; pr < 4; pr++) {
        // K (B-role, non-trans): rows = keys (16 per pr), col-half lane&8
        ks_addr[pr] = smem_u32(&Ks[(pr * 16 + ((lane >> 4) << 3) + (lane & 7)) * ASTR + (lane & 8)]);
        // V (B-role, TRANS): rows = keys (k-step selects block of 16), cols = d-tile pr*16
        vs_addr[pr] = smem_u32(&Vs[(lane & 15) * ASTR + pr * 16 + ((lane >> 4) << 3)]);
    }

    const int kr0 = tid >> 3, kr1 = (tid + 256) >> 3;
    uint4 kreg[2], vreg[2];
    auto pf_k = [&](int kt) {
        const __half* Kt = Kb + (size_t)kt * 64 * QSTR;
        kreg[0] = *(const uint4*)(Kt + (size_t)kr0 * QSTR + sc8);
        kreg[1] = *(const uint4*)(Kt + (size_t)kr1 * QSTR + sc8);
    };
    auto pf_v = [&](int kt) {
        const __half* Vp = Vb + (size_t)kt * 64 * QSTR;
        vreg[0] = *(const uint4*)(Vp + (size_t)kr0 * QSTR + sc8);
        vreg[1] = *(const uint4*)(Vp + (size_t)kr1 * QSTR + sc8);
    };

    float m_i[2], l_i[2];
    float oc[8][4];
    m_i[0] = m_i[1] = -INFINITY;
    l_i[0] = l_i[1] = 0.0f;
    #pragma unroll
    for (int nt = 0; nt < 8; nt++)
        #pragma unroll
        for (int j = 0; j < 4; j++) oc[nt][j] = 0.0f;

    pf_k(0); pf_v(0);

    for (int kt = 0; kt < SEQ / 64; kt++) {
        __syncthreads();
        *(uint4*)&Ks[kr0 * ASTR + sc8] = kreg[0];
        *(uint4*)&Ks[kr1 * ASTR + sc8] = kreg[1];
        *(uint4*)&Vs[kr0 * ASTR + sc8] = vreg[0];
        *(uint4*)&Vs[kr1 * ASTR + sc8] = vreg[1];
        __syncthreads();

        const bool more = (kt + 1) < (SEQ / 64);
        if (more) pf_k(kt + 1);

        // ---- S = Q . K^T : 4 k16 steps over d ----
        float scv[8][4];
        #pragma unroll
        for (int nt = 0; nt < 8; nt++)
            #pragma unroll
            for (int j = 0; j < 4; j++) scv[nt][j] = 0.0f;

        #pragma unroll
        for (int ks = 0; ks < 4; ks++) {
            const uint32_t kb = ks * 32;   // 16 halves
            uint32_t a[4];
            ldsm_x4(a, qs_addr + kb);
            #pragma unroll
            for (int pr = 0; pr < 4; pr++) {
                uint32_t bb[4];
                ldsm_x4(bb, ks_addr[pr] + kb);
                mma_f16(scv[2 * pr],     a, bb);
                mma_f16(scv[2 * pr + 1], a, bb + 2);
            }
        }

        // ---- online softmax (rows lrow, lrow+8; 4 lanes share a row) ----
        #pragma unroll
        for (int rr = 0; rr < 2; rr++) {
            const int i0 = rr * 2;
            float tmax = -INFINITY;
            #pragma unroll
            for (int nt = 0; nt < 8; nt++) {
                scv[nt][i0]     *= 0.125f;
                scv[nt][i0 + 1] *= 0.125f;
                tmax = fmaxf(tmax, fmaxf(scv[nt][i0], scv[nt][i0 + 1]));
            }
            tmax = fmaxf(tmax, __shfl_xor_sync(0xffffffffu, tmax, 1));
            tmax = fmaxf(tmax, __shfl_xor_sync(0xffffffffu, tmax, 2));
            float mnew  = fmaxf(m_i[rr], tmax);
            float alpha = __expf(m_i[rr] - mnew);
            float rsum  = 0.0f;
            #pragma unroll
            for (int nt = 0; nt < 8; nt++) {
                float p0 = __expf(scv[nt][i0]     - mnew);
                float p1 = __expf(scv[nt][i0 + 1] - mnew);
                rsum += p0 + p1;
                oc[nt][i0]     *= alpha;
                oc[nt][i0 + 1] *= alpha;
                *(__half2*)&Ps[(wrow + lrow + rr * 8) * ASTR + nt * 8 + 2 * lcol] =
                    __floats2half2_rn(p0, p1);
            }
            rsum += __shfl_xor_sync(0xffffffffu, rsum, 1);
            rsum += __shfl_xor_sync(0xffffffffu, rsum, 2);
            l_i[rr] = l_i[rr] * alpha + rsum;
            m_i[rr] = mnew;
        }
        __syncwarp();

        if (more) pf_v(kt + 1);

        // ---- O += P . V : 4 k16 steps over keys; V frags via ldmatrix.trans ----
        #pragma unroll
        for (int ks = 0; ks < 4; ks++) {
            uint32_t a[4];
            ldsm_x4(a, ps_addr + ks * 32);
            const uint32_t vko = (uint32_t)(ks * 16 * ASTR * 2);  // key-block offset
            #pragma unroll
            for (int pr = 0; pr < 4; pr++) {
                uint32_t bb[4];
                ldsm_x4_t(bb, vs_addr[pr] + vko);
                mma_f16(oc[2 * pr],     a, bb);
                mma_f16(oc[2 * pr + 1], a, bb + 2);
            }
        }
    }

    // Epilogue: normalize, convert fp16 (feeds Wo GEMM), write [B,T,D]
    __half* Ob = O + ((size_t)b * SEQ + (size_t)qt * 128) * EMBED + h * HDIM;
    #pragma unroll
    for (int rr = 0; rr < 2; rr++) {
        const float inv = 1.0f / l_i[rr];
        const int i0 = rr * 2;
        __half* orow = Ob + (size_t)(wrow + lrow + rr * 8) * EMBED + 2 * lcol;
        #pragma unroll
        for (int nt = 0; nt < 8; nt++)
            *(__half2*)(orow + nt * 8) =
                __floats2half2_rn(oc[nt][i0] * inv, oc[nt][i0 + 1] * inv);
    }
}

// ---------------------------------------------------------------------------
extern "C" void kernel_launch(void* const* d_in, const int* in_sizes, int n_in,
                              void* d_out, int out_size) {
    const float* x  = (const float*)d_in[0];
    const float* Wq = (const float*)d_in[1];
    const float* Wk = (const float*)d_in[2];
    const float* Wv = (const float*)d_in[3];
    const float* Wo = (const float*)d_in[4];
    float* out = (float*)d_out;

    __half *QKVh, *Oh, *Xh, *Wh;
    cudaGetSymbolAddress((void**)&QKVh, g_QKVh);
    cudaGetSymbolAddress((void**)&Oh, g_Oh);
    cudaGetSymbolAddress((void**)&Xh, g_Xh);
    cudaGetSymbolAddress((void**)&Wh, g_Wh);

    const size_t WSZ = (size_t)EMBED * EMBED;

    // Convert inputs to fp16 (RN; same 11-bit mantissa as tf32 for O(1) data)
    {
        const int xn8 = (MTOT * EMBED) / 8;          // 1048576
        const int wn8 = (int)(WSZ / 8);              // 131072
        f32_to_f16_kernel<<<xn8 / 256, 256>>>(Xh, x, xn8);
        f32_to_f16_w4<<<(4 * wn8) / 256, 256>>>(Wh, Wq, Wk, Wv, Wo, wn8);
    }

    // Fused QKV projection: [8192,1024] x [3072,1024]^T -> [8192,3072] fp16
    gemm_h<<<dim3(QSTR / 128, MTOT / 128), 256>>>(Xh, Wh, nullptr, QKVh, MTOT, QSTR, EMBED);

    const int attn_smem = (128 + 64 + 64 + 128) * ASTR * (int)sizeof(__half);  // 55296
    cudaFuncSetAttribute(attn_h, cudaFuncAttributeMaxDynamicSharedMemorySize, attn_smem);
    attn_h<<<dim3(SEQ / 128, BATCH * NHEADS), 256, attn_smem>>>(QKVh, Oh);

    // Final projection: fp32 output
    gemm_h<<<dim3(EMBED / 128, MTOT / 128), 256>>>(Oh, Wh + 3 * WSZ, out, nullptr, MTOT, EMBED, EMBED);
}

// round 16
// speedup vs baseline: 7.5453x; 1.0737x over previous
#include <cuda_runtime.h>
#include <cuda.h>
#include <cuda_fp16.h>
#include <math.h>
#include <stdint.h>

#define EMBED  1024
#define NHEADS 16
#define HDIM   64
#define BATCH  4
#define SEQ    2048
#define MTOT   (BATCH * SEQ)   // 8192
#define QSTR   3072            // fused QKV row stride (halves)

// Scratch (allocation-free rule: __device__ globals)
__device__ __half g_QKVh[(size_t)MTOT * QSTR];        // fused Q|K|V, fp16
__device__ __half g_Oh[(size_t)MTOT * EMBED];         // attention out, fp16
__device__ __half g_Xh[(size_t)MTOT * EMBED];         // x in fp16
__device__ __half g_Wh[(size_t)4 * EMBED * EMBED];    // Wq|Wk|Wv|Wo in fp16

// ---------------------------------------------------------------------------
// Helpers (baseline PTX only — no sm_103a-suffixed features)
// ---------------------------------------------------------------------------
__device__ __forceinline__ uint32_t smem_u32(const void* p) {
    uint32_t a;
    asm("{ .reg .u64 t; cvta.to.shared.u64 t, %1; cvt.u32.u64 %0, t; }" : "=r"(a) : "l"(p));
    return a;
}
__device__ __forceinline__ void cp_async16(uint32_t dst, const void* src) {
    asm volatile("cp.async.cg.shared.global [%0], [%1], 16;" :: "r"(dst), "l"(src) : "memory");
}
__device__ __forceinline__ void cp_commit() {
    asm volatile("cp.async.commit_group;" ::: "memory");
}
template <int N>
__device__ __forceinline__ void cp_wait() {
    asm volatile("cp.async.wait_group %0;" :: "n"(N) : "memory");
}
// fp16 MMA, fp32 accumulate: D(16x8) += A(16x16) * B(16x8)
__device__ __forceinline__ void mma_f16(float* d, const uint32_t* a, const uint32_t* b) {
    asm volatile(
        "mma.sync.aligned.m16n8k16.row.col.f32.f16.f16.f32 "
        "{%0,%1,%2,%3}, {%4,%5,%6,%7}, {%8,%9}, {%0,%1,%2,%3};"
        : "+f"(d[0]), "+f"(d[1]), "+f"(d[2]), "+f"(d[3])
        : "r"(a[0]), "r"(a[1]), "r"(a[2]), "r"(a[3]), "r"(b[0]), "r"(b[1]));
}
__device__ __forceinline__ void ldsm_x4(uint32_t* r, uint32_t addr) {
    asm volatile("ldmatrix.sync.aligned.m8n8.x4.shared.b16 {%0,%1,%2,%3}, [%4];"
        : "=r"(r[0]), "=r"(r[1]), "=r"(r[2]), "=r"(r[3]) : "r"(addr));
}
__device__ __forceinline__ void ldsm_x4_t(uint32_t* r, uint32_t addr) {
    asm volatile("ldmatrix.sync.aligned.m8n8.x4.trans.shared.b16 {%0,%1,%2,%3}, [%4];"
        : "=r"(r[0]), "=r"(r[1]), "=r"(r[2]), "=r"(r[3]) : "r"(addr));
}

// ---------------------------------------------------------------------------
// fp32 -> fp16 conversion kernels (8 floats / thread)
// ---------------------------------------------------------------------------
__global__ void f32_to_f16_kernel(__half* __restrict__ dst, const float* __restrict__ src, int n8) {
    int i = blockIdx.x * blockDim.x + threadIdx.x;
    if (i < n8) {
        const float4* s = (const float4*)src + 2 * (size_t)i;
        float4 v0 = s[0], v1 = s[1];
        __half2 h0 = __floats2half2_rn(v0.x, v0.y);
        __half2 h1 = __floats2half2_rn(v0.z, v0.w);
        __half2 h2 = __floats2half2_rn(v1.x, v1.y);
        __half2 h3 = __floats2half2_rn(v1.z, v1.w);
        uint4 o;
        o.x = *(uint32_t*)&h0; o.y = *(uint32_t*)&h1;
        o.z = *(uint32_t*)&h2; o.w = *(uint32_t*)&h3;
        ((uint4*)dst)[i] = o;
    }
}
__global__ void f32_to_f16_w4(__half* __restrict__ dst,
                              const float* __restrict__ w0, const float* __restrict__ w1,
                              const float* __restrict__ w2, const float* __restrict__ w3,
                              int n8each) {
    int i = blockIdx.x * blockDim.x + threadIdx.x;
    int which = i / n8each;
    int j = i - which * n8each;
    const float* src = (which == 0) ? w0 : (which == 1) ? w1 : (which == 2) ? w2 : w3;
    const float4* s = (const float4*)src + 2 * (size_t)j;
    float4 v0 = s[0], v1 = s[1];
    __half2 h0 = __floats2half2_rn(v0.x, v0.y);
    __half2 h1 = __floats2half2_rn(v0.z, v0.w);
    __half2 h2 = __floats2half2_rn(v1.x, v1.y);
    __half2 h3 = __floats2half2_rn(v1.z, v1.w);
    uint4 o;
    o.x = *(uint32_t*)&h0; o.y = *(uint32_t*)&h1;
    o.z = *(uint32_t*)&h2; o.w = *(uint32_t*)&h3;
    ((uint4*)dst)[i] = o;
}

// ---------------------------------------------------------------------------
// fp16 mma.sync GEMM (NT): C[m,n] = sum_k A[m,k] * W[n,k]   (unchanged R15)
// ---------------------------------------------------------------------------
#define GBK   32
#define GSTR  40
#define GBUF_BYTES (128 * GSTR * 2)

__global__ __launch_bounds__(256, 2)
void gemm_h(const __half* __restrict__ A, const __half* __restrict__ W,
            float* __restrict__ Cf, __half* __restrict__ Ch, int M, int N, int K) {
    __shared__ __align__(16) __half As[2][128][GSTR];
    __shared__ __align__(16) __half Bs[2][128][GSTR];

    const int tid  = threadIdx.x;
    const int wid  = tid >> 5;
    const int lane = tid & 31;
    const int bm   = blockIdx.y * 128;
    const int bn   = blockIdx.x * 128;

    const int wm = (wid & 1) * 64;
    const int wn = (wid >> 1) * 32;
    const int lrow = lane >> 2;
    const int lcol = lane & 3;

    const int r0 = tid >> 2, c0 = (tid & 3) * 8;
    const int r1 = (tid + 256) >> 2, c1 = ((tid + 256) & 3) * 8;

    float acc[4][4][4];
    #pragma unroll
    for (int mt = 0; mt < 4; mt++)
        #pragma unroll
        for (int nt = 0; nt < 4; nt++)
            #pragma unroll
            for (int j = 0; j < 4; j++) acc[mt][nt][j] = 0.0f;

    uint32_t a_addr[4], b_addr[2];
    #pragma unroll
    for (int mt = 0; mt < 4; mt++)
        a_addr[mt] = smem_u32(&As[0][wm + mt * 16 + (lane & 15)][(lane >> 4) << 3]);
    #pragma unroll
    for (int pr = 0; pr < 2; pr++)
        b_addr[pr] = smem_u32(&Bs[0][wn + pr * 16 + ((lane >> 4) << 3) + (lane & 7)][lane & 8]);

    const int NK = K / GBK;

    auto issue = [&](int kt, int buf) {
        const __half* Ap = A + (size_t)bm * K + kt * GBK;
        const __half* Wp = W + (size_t)bn * K + kt * GBK;
        cp_async16(smem_u32(&As[buf][r0][c0]), Ap + (size_t)r0 * K + c0);
        cp_async16(smem_u32(&As[buf][r1][c1]), Ap + (size_t)r1 * K + c1);
        cp_async16(smem_u32(&Bs[buf][r0][c0]), Wp + (size_t)r0 * K + c0);
        cp_async16(smem_u32(&Bs[buf][r1][c1]), Wp + (size_t)r1 * K + c1);
    };

    issue(0, 0);
    cp_commit();

    for (int kt = 0; kt < NK; kt++) {
        const int buf = kt & 1;
        const uint32_t bo = (uint32_t)buf * GBUF_BYTES;
        if (kt + 1 < NK) {
            issue(kt + 1, buf ^ 1);
            cp_commit();
            cp_wait<1>();
        } else {
            cp_wait<0>();
        }
        __syncthreads();

        #pragma unroll
        for (int ks = 0; ks < 2; ks++) {
            const uint32_t kb = ks * 32;
            uint32_t af[4][4];
            #pragma unroll
            for (int mt = 0; mt < 4; mt++)
                ldsm_x4(af[mt], a_addr[mt] + bo + kb);
            #pragma unroll
            for (int pr = 0; pr < 2; pr++) {
                uint32_t bb[4];
                ldsm_x4(bb, b_addr[pr] + bo + kb);
                #pragma unroll
                for (int mt = 0; mt < 4; mt++) {
                    mma_f16(acc[mt][2 * pr],     af[mt], bb);
                    mma_f16(acc[mt][2 * pr + 1], af[mt], bb + 2);
                }
            }
        }
        __syncthreads();
    }

    #pragma unroll
    for (int mt = 0; mt < 4; mt++) {
        #pragma unroll
        for (int nt = 0; nt < 4; nt++) {
            const int row = bm + wm + mt * 16 + lrow;
            const int col = bn + wn + nt * 8 + 2 * lcol;
            if (Ch) {
                __half2 h0 = __floats2half2_rn(acc[mt][nt][0], acc[mt][nt][1]);
                __half2 h1 = __floats2half2_rn(acc[mt][nt][2], acc[mt][nt][3]);
                *(__half2*)(Ch + (size_t)row * N + col) = h0;
                *(__half2*)(Ch + (size_t)(row + 8) * N + col) = h1;
            } else {
                *(float2*)(Cf + (size_t)row * N + col) =
                    make_float2(acc[mt][nt][0], acc[mt][nt][1]);
                *(float2*)(Cf + (size_t)(row + 8) * N + col) =
                    make_float2(acc[mt][nt][2], acc[mt][nt][3]);
            }
        }
    }
}

// ---------------------------------------------------------------------------
// fp16 mma.sync flash attention, P held in registers.
// The m16n8k16 C-fragment of S maps EXACTLY onto the A-fragment needed for
// P.V: pa[ks] = { pack(c01 of nt=2ks), pack(c23 of nt=2ks),
//                 pack(c01 of nt=2ks+1), pack(c23 of nt=2ks+1) }.
// So softmax converts S accumulators straight into PV A-operands — no P smem,
// no STS, no ldsm, no syncwarp. 1/sqrt(64) folded into Q at staging (exact).
// ---------------------------------------------------------------------------
#define ASTR 72   // smem row stride (halves) = 144B -> conflict-free ldsm

__global__ __launch_bounds__(256, 2)
void attn_h(const __half* __restrict__ QKV, __half* __restrict__ O) {
    extern __shared__ __align__(16) __half smh[];
    __half* Qs = smh;                  // [128][ASTR]  q rows, d cols (pre-scaled)
    __half* Ks = Qs + 128 * ASTR;      // [64][ASTR]   key rows, d cols
    __half* Vs = Ks + 64 * ASTR;       // [64][ASTR]   key rows, d cols (natural)

    const int tid  = threadIdx.x;
    const int wid  = tid >> 5;
    const int lane = tid & 31;
    const int lrow = lane >> 2;
    const int lcol = lane & 3;
    const int wrow = wid * 16;

    const int qt = blockIdx.x;
    const int b  = blockIdx.y >> 4;
    const int h  = blockIdx.y & 15;

    const __half* Qb = QKV + ((size_t)b * SEQ + (size_t)qt * 128) * QSTR + h * HDIM;
    const __half* Kb = QKV + (size_t)b * SEQ * QSTR + EMBED     + h * HDIM;
    const __half* Vb = QKV + (size_t)b * SEQ * QSTR + 2 * EMBED + h * HDIM;

    const int sc8 = (tid & 7) * 8;

    // Stage Q tile [128][64], pre-scaled by 1/8 (exact power-of-two in fp16)
    {
        const __half2 sc = __floats2half2_rn(0.125f, 0.125f);
        #pragma unroll
        for (int it = 0; it < 4; it++) {
            int f = tid + it * 256;
            int r = f >> 3;
            int c = (f & 7) * 8;
            uint4 v = *(const uint4*)(Qb + (size_t)r * QSTR + c);
            __half2* hp = (__half2*)&v;
            hp[0] = __hmul2(hp[0], sc);
            hp[1] = __hmul2(hp[1], sc);
            hp[2] = __hmul2(hp[2], sc);
            hp[3] = __hmul2(hp[3], sc);
            *(uint4*)&Qs[r * ASTR + c] = v;
        }
    }

    // ldmatrix base addresses
    uint32_t qs_addr = smem_u32(&Qs[(wrow + (lane & 15)) * ASTR + ((lane >> 4) << 3)]);
    uint32_t ks_addr[4], vs_addr[4];
    #pragma unroll
    for (int pr = 0; pr < 4; pr++) {
        ks_addr[pr] = smem_u32(&Ks[(pr * 16 + ((lane >> 4) << 3) + (lane & 7)) * ASTR + (lane & 8)]);
        vs_addr[pr] = smem_u32(&Vs[(lane & 15) * ASTR + pr * 16 + ((lane >> 4) << 3)]);
    }

    const int kr0 = tid >> 3, kr1 = (tid + 256) >> 3;
    uint4 kreg[2], vreg[2];
    auto pf_k = [&](int kt) {
        const __half* Kt = Kb + (size_t)kt * 64 * QSTR;
        kreg[0] = *(const uint4*)(Kt + (size_t)kr0 * QSTR + sc8);
        kreg[1] = *(const uint4*)(Kt + (size_t)kr1 * QSTR + sc8);
    };
    auto pf_v = [&](int kt) {
        const __half* Vp = Vb + (size_t)kt * 64 * QSTR;
        vreg[0] = *(const uint4*)(Vp + (size_t)kr0 * QSTR + sc8);
        vreg[1] = *(const uint4*)(Vp + (size_t)kr1 * QSTR + sc8);
    };

    float m_i[2], l_i[2];
    float oc[8][4];
    m_i[0] = m_i[1] = -INFINITY;
    l_i[0] = l_i[1] = 0.0f;
    #pragma unroll
    for (int nt = 0; nt < 8; nt++)
        #pragma unroll
        for (int j = 0; j < 4; j++) oc[nt][j] = 0.0f;

    pf_k(0); pf_v(0);

    for (int kt = 0; kt < SEQ / 64; kt++) {
        __syncthreads();
        *(uint4*)&Ks[kr0 * ASTR + sc8] = kreg[0];
        *(uint4*)&Ks[kr1 * ASTR + sc8] = kreg[1];
        *(uint4*)&Vs[kr0 * ASTR + sc8] = vreg[0];
        *(uint4*)&Vs[kr1 * ASTR + sc8] = vreg[1];
        __syncthreads();

        const bool more = (kt + 1) < (SEQ / 64);
        if (more) pf_k(kt + 1);

        // ---- S = (Q/8) . K^T : 4 k16 steps over d ----
        float scv[8][4];
        #pragma unroll
        for (int nt = 0; nt < 8; nt++)
            #pragma unroll
            for (int j = 0; j < 4; j++) scv[nt][j] = 0.0f;

        #pragma unroll
        for (int ks = 0; ks < 4; ks++) {
            const uint32_t kb = ks * 32;
            uint32_t a[4];
            ldsm_x4(a, qs_addr + kb);
            #pragma unroll
            for (int pr = 0; pr < 4; pr++) {
                uint32_t bb[4];
                ldsm_x4(bb, ks_addr[pr] + kb);
                mma_f16(scv[2 * pr],     a, bb);
                mma_f16(scv[2 * pr + 1], a, bb + 2);
            }
        }

        // ---- online softmax; P packed straight into PV A-fragments ----
        uint32_t pa[4][4];
        #pragma unroll
        for (int rr = 0; rr < 2; rr++) {
            const int i0 = rr * 2;
            float tmax = -INFINITY;
            #pragma unroll
            for (int nt = 0; nt < 8; nt++)
                tmax = fmaxf(tmax, fmaxf(scv[nt][i0], scv[nt][i0 + 1]));
            tmax = fmaxf(tmax, __shfl_xor_sync(0xffffffffu, tmax, 1));
            tmax = fmaxf(tmax, __shfl_xor_sync(0xffffffffu, tmax, 2));
            float mnew  = fmaxf(m_i[rr], tmax);
            float alpha = __expf(m_i[rr] - mnew);
            float rsum  = 0.0f;
            #pragma unroll
            for (int nt = 0; nt < 8; nt++) {
                float p0 = __expf(scv[nt][i0]     - mnew);
                float p1 = __expf(scv[nt][i0 + 1] - mnew);
                rsum += p0 + p1;
                oc[nt][i0]     *= alpha;
                oc[nt][i0 + 1] *= alpha;
                __half2 ph = __floats2half2_rn(p0, p1);
                pa[nt >> 1][(nt & 1) * 2 + rr] = *(uint32_t*)&ph;
            }
            rsum += __shfl_xor_sync(0xffffffffu, rsum, 1);
            rsum += __shfl_xor_sync(0xffffffffu, rsum, 2);
            l_i[rr] = l_i[rr] * alpha + rsum;
            m_i[rr] = mnew;
        }

        if (more) pf_v(kt + 1);

        // ---- O += P . V : A from registers, V frags via ldmatrix.trans ----
        #pragma unroll
        for (int ks = 0; ks < 4; ks++) {
            const uint32_t vko = (uint32_t)(ks * 16 * ASTR * 2);
            #pragma unroll
            for (int pr = 0; pr < 4; pr++) {
                uint32_t bb[4];
                ldsm_x4_t(bb, vs_addr[pr] + vko);
                mma_f16(oc[2 * pr],     pa[ks], bb);
                mma_f16(oc[2 * pr + 1], pa[ks], bb + 2);
            }
        }
    }

    // Epilogue: normalize, convert fp16 (feeds Wo GEMM), write [B,T,D]
    __half* Ob = O + ((size_t)b * SEQ + (size_t)qt * 128) * EMBED + h * HDIM;
    #pragma unroll
    for (int rr = 0; rr < 2; rr++) {
        const float inv = 1.0f / l_i[rr];
        const int i0 = rr * 2;
        __half* orow = Ob + (size_t)(wrow + lrow + rr * 8) * EMBED + 2 * lcol;
        #pragma unroll
        for (int nt = 0; nt < 8; nt++)
            *(__half2*)(orow + nt * 8) =
                __floats2half2_rn(oc[nt][i0] * inv, oc[nt][i0 + 1] * inv);
    }
}

// ---------------------------------------------------------------------------
extern "C" void kernel_launch(void* const* d_in, const int* in_sizes, int n_in,
                              void* d_out, int out_size) {
    const float* x  = (const float*)d_in[0];
    const float* Wq = (const float*)d_in[1];
    const float* Wk = (const float*)d_in[2];
    const float* Wv = (const float*)d_in[3];
    const float* Wo = (const float*)d_in[4];
    float* out = (float*)d_out;

    __half *QKVh, *Oh, *Xh, *Wh;
    cudaGetSymbolAddress((void**)&QKVh, g_QKVh);
    cudaGetSymbolAddress((void**)&Oh, g_Oh);
    cudaGetSymbolAddress((void**)&Xh, g_Xh);
    cudaGetSymbolAddress((void**)&Wh, g_Wh);

    const size_t WSZ = (size_t)EMBED * EMBED;

    // Convert inputs to fp16
    {
        const int xn8 = (MTOT * EMBED) / 8;
        const int wn8 = (int)(WSZ / 8);
        f32_to_f16_kernel<<<xn8 / 256, 256>>>(Xh, x, xn8);
        f32_to_f16_w4<<<(4 * wn8) / 256, 256>>>(Wh, Wq, Wk, Wv, Wo, wn8);
    }

    // Fused QKV projection: [8192,1024] x [3072,1024]^T -> [8192,3072] fp16
    gemm_h<<<dim3(QSTR / 128, MTOT / 128), 256>>>(Xh, Wh, nullptr, QKVh, MTOT, QSTR, EMBED);

    const int attn_smem = (128 + 64 + 64) * ASTR * (int)sizeof(__half);  // 36864
    cudaFuncSetAttribute(attn_h, cudaFuncAttributeMaxDynamicSharedMemorySize, attn_smem);
    attn_h<<<dim3(SEQ / 128, BATCH * NHEADS), 256, attn_smem>>>(QKVh, Oh);

    // Final projection: fp32 output
    gemm_h<<<dim3(EMBED / 128, MTOT / 128), 256>>>(Oh, Wh + 3 * WSZ, out, nullptr, MTOT, EMBED, EMBED);
}

// round 17
// speedup vs baseline: 7.8771x; 1.0440x over previous
#include <cuda_runtime.h>
#include <cuda.h>
#include <cuda_fp16.h>
#include <math.h>
#include <stdint.h>

#define EMBED  1024
#define NHEADS 16
#define HDIM   64
#define BATCH  4
#define SEQ    2048
#define MTOT   (BATCH * SEQ)   // 8192
#define QSTR   3072            // fused QKV row stride (halves)

// Scratch (allocation-free rule: __device__ globals)
__device__ __half g_QKVh[(size_t)MTOT * QSTR];        // fused Q|K|V, fp16
__device__ __half g_Oh[(size_t)MTOT * EMBED];         // attention out, fp16
__device__ __half g_Xh[(size_t)MTOT * EMBED];         // x in fp16
__device__ __half g_Wh[(size_t)4 * EMBED * EMBED];    // Wq|Wk|Wv|Wo in fp16

// ---------------------------------------------------------------------------
// Helpers (baseline PTX only — no sm_103a-suffixed features)
// ---------------------------------------------------------------------------
__device__ __forceinline__ uint32_t smem_u32(const void* p) {
    uint32_t a;
    asm("{ .reg .u64 t; cvta.to.shared.u64 t, %1; cvt.u32.u64 %0, t; }" : "=r"(a) : "l"(p));
    return a;
}
__device__ __forceinline__ void cp_async16(uint32_t dst, const void* src) {
    asm volatile("cp.async.cg.shared.global [%0], [%1], 16;" :: "r"(dst), "l"(src) : "memory");
}
__device__ __forceinline__ void cp_commit() {
    asm volatile("cp.async.commit_group;" ::: "memory");
}
template <int N>
__device__ __forceinline__ void cp_wait() {
    asm volatile("cp.async.wait_group %0;" :: "n"(N) : "memory");
}
// fp16 MMA, fp32 accumulate: D(16x8) += A(16x16) * B(16x8)
__device__ __forceinline__ void mma_f16(float* d, const uint32_t* a, const uint32_t* b) {
    asm volatile(
        "mma.sync.aligned.m16n8k16.row.col.f32.f16.f16.f32 "
        "{%0,%1,%2,%3}, {%4,%5,%6,%7}, {%8,%9}, {%0,%1,%2,%3};"
        : "+f"(d[0]), "+f"(d[1]), "+f"(d[2]), "+f"(d[3])
        : "r"(a[0]), "r"(a[1]), "r"(a[2]), "r"(a[3]), "r"(b[0]), "r"(b[1]));
}
__device__ __forceinline__ void ldsm_x4(uint32_t* r, uint32_t addr) {
    asm volatile("ldmatrix.sync.aligned.m8n8.x4.shared.b16 {%0,%1,%2,%3}, [%4];"
        : "=r"(r[0]), "=r"(r[1]), "=r"(r[2]), "=r"(r[3]) : "r"(addr));
}
__device__ __forceinline__ void ldsm_x4_t(uint32_t* r, uint32_t addr) {
    asm volatile("ldmatrix.sync.aligned.m8n8.x4.trans.shared.b16 {%0,%1,%2,%3}, [%4];"
        : "=r"(r[0]), "=r"(r[1]), "=r"(r[2]), "=r"(r[3]) : "r"(addr));
}
// two fp16 exp2 per MUFU op; result packed half2 (= PV A-fragment word)
__device__ __forceinline__ uint32_t ex2_f16x2(uint32_t x) {
    uint32_t r;
    asm("ex2.approx.f16x2 %0, %1;" : "=r"(r) : "r"(x));
    return r;
}

// ---------------------------------------------------------------------------
// fp32 -> fp16 conversion kernels (8 floats / thread)
// ---------------------------------------------------------------------------
__global__ void f32_to_f16_kernel(__half* __restrict__ dst, const float* __restrict__ src, int n8) {
    int i = blockIdx.x * blockDim.x + threadIdx.x;
    if (i < n8) {
        const float4* s = (const float4*)src + 2 * (size_t)i;
        float4 v0 = s[0], v1 = s[1];
        __half2 h0 = __floats2half2_rn(v0.x, v0.y);
        __half2 h1 = __floats2half2_rn(v0.z, v0.w);
        __half2 h2 = __floats2half2_rn(v1.x, v1.y);
        __half2 h3 = __floats2half2_rn(v1.z, v1.w);
        uint4 o;
        o.x = *(uint32_t*)&h0; o.y = *(uint32_t*)&h1;
        o.z = *(uint32_t*)&h2; o.w = *(uint32_t*)&h3;
        ((uint4*)dst)[i] = o;
    }
}
__global__ void f32_to_f16_w4(__half* __restrict__ dst,
                              const float* __restrict__ w0, const float* __restrict__ w1,
                              const float* __restrict__ w2, const float* __restrict__ w3,
                              int n8each) {
    int i = blockIdx.x * blockDim.x + threadIdx.x;
    int which = i / n8each;
    int j = i - which * n8each;
    const float* src = (which == 0) ? w0 : (which == 1) ? w1 : (which == 2) ? w2 : w3;
    const float4* s = (const float4*)src + 2 * (size_t)j;
    float4 v0 = s[0], v1 = s[1];
    __half2 h0 = __floats2half2_rn(v0.x, v0.y);
    __half2 h1 = __floats2half2_rn(v0.z, v0.w);
    __half2 h2 = __floats2half2_rn(v1.x, v1.y);
    __half2 h3 = __floats2half2_rn(v1.z, v1.w);
    uint4 o;
    o.x = *(uint32_t*)&h0; o.y = *(uint32_t*)&h1;
    o.z = *(uint32_t*)&h2; o.w = *(uint32_t*)&h3;
    ((uint4*)dst)[i] = o;
}

// ---------------------------------------------------------------------------
// fp16 mma.sync GEMM (NT): C[m,n] = sum_k A[m,k] * W[n,k]   (unchanged)
// ---------------------------------------------------------------------------
#define GBK   32
#define GSTR  40
#define GBUF_BYTES (128 * GSTR * 2)

__global__ __launch_bounds__(256, 2)
void gemm_h(const __half* __restrict__ A, const __half* __restrict__ W,
            float* __restrict__ Cf, __half* __restrict__ Ch, int M, int N, int K) {
    __shared__ __align__(16) __half As[2][128][GSTR];
    __shared__ __align__(16) __half Bs[2][128][GSTR];

    const int tid  = threadIdx.x;
    const int wid  = tid >> 5;
    const int lane = tid & 31;
    const int bm   = blockIdx.y * 128;
    const int bn   = blockIdx.x * 128;

    const int wm = (wid & 1) * 64;
    const int wn = (wid >> 1) * 32;
    const int lrow = lane >> 2;
    const int lcol = lane & 3;

    const int r0 = tid >> 2, c0 = (tid & 3) * 8;
    const int r1 = (tid + 256) >> 2, c1 = ((tid + 256) & 3) * 8;

    float acc[4][4][4];
    #pragma unroll
    for (int mt = 0; mt < 4; mt++)
        #pragma unroll
        for (int nt = 0; nt < 4; nt++)
            #pragma unroll
            for (int j = 0; j < 4; j++) acc[mt][nt][j] = 0.0f;

    uint32_t a_addr[4], b_addr[2];
    #pragma unroll
    for (int mt = 0; mt < 4; mt++)
        a_addr[mt] = smem_u32(&As[0][wm + mt * 16 + (lane & 15)][(lane >> 4) << 3]);
    #pragma unroll
    for (int pr = 0; pr < 2; pr++)
        b_addr[pr] = smem_u32(&Bs[0][wn + pr * 16 + ((lane >> 4) << 3) + (lane & 7)][lane & 8]);

    const int NK = K / GBK;

    auto issue = [&](int kt, int buf) {
        const __half* Ap = A + (size_t)bm * K + kt * GBK;
        const __half* Wp = W + (size_t)bn * K + kt * GBK;
        cp_async16(smem_u32(&As[buf][r0][c0]), Ap + (size_t)r0 * K + c0);
        cp_async16(smem_u32(&As[buf][r1][c1]), Ap + (size_t)r1 * K + c1);
        cp_async16(smem_u32(&Bs[buf][r0][c0]), Wp + (size_t)r0 * K + c0);
        cp_async16(smem_u32(&Bs[buf][r1][c1]), Wp + (size_t)r1 * K + c1);
    };

    issue(0, 0);
    cp_commit();

    for (int kt = 0; kt < NK; kt++) {
        const int buf = kt & 1;
        const uint32_t bo = (uint32_t)buf * GBUF_BYTES;
        if (kt + 1 < NK) {
            issue(kt + 1, buf ^ 1);
            cp_commit();
            cp_wait<1>();
        } else {
            cp_wait<0>();
        }
        __syncthreads();

        #pragma unroll
        for (int ks = 0; ks < 2; ks++) {
            const uint32_t kb = ks * 32;
            uint32_t af[4][4];
            #pragma unroll
            for (int mt = 0; mt < 4; mt++)
                ldsm_x4(af[mt], a_addr[mt] + bo + kb);
            #pragma unroll
            for (int pr = 0; pr < 2; pr++) {
                uint32_t bb[4];
                ldsm_x4(bb, b_addr[pr] + bo + kb);
                #pragma unroll
                for (int mt = 0; mt < 4; mt++) {
                    mma_f16(acc[mt][2 * pr],     af[mt], bb);
                    mma_f16(acc[mt][2 * pr + 1], af[mt], bb + 2);
                }
            }
        }
        __syncthreads();
    }

    #pragma unroll
    for (int mt = 0; mt < 4; mt++) {
        #pragma unroll
        for (int nt = 0; nt < 4; nt++) {
            const int row = bm + wm + mt * 16 + lrow;
            const int col = bn + wn + nt * 8 + 2 * lcol;
            if (Ch) {
                __half2 h0 = __floats2half2_rn(acc[mt][nt][0], acc[mt][nt][1]);
                __half2 h1 = __floats2half2_rn(acc[mt][nt][2], acc[mt][nt][3]);
                *(__half2*)(Ch + (size_t)row * N + col) = h0;
                *(__half2*)(Ch + (size_t)(row + 8) * N + col) = h1;
            } else {
                *(float2*)(Cf + (size_t)row * N + col) =
                    make_float2(acc[mt][nt][0], acc[mt][nt][1]);
                *(float2*)(Cf + (size_t)(row + 8) * N + col) =
                    make_float2(acc[mt][nt][2], acc[mt][nt][3]);
            }
        }
    }
}

// ---------------------------------------------------------------------------
// fp16 mma.sync flash attention, log2-domain softmax.
//  - Q pre-scaled by 0.125*log2(e) at staging -> S is log2-domain logits.
//  - P = ex2.approx.f16x2(s - m): one MUFU per PAIR, result IS the packed
//    half2 A-fragment word for P.V (no smem roundtrip, no separate pack).
//  - Row sums l computed by MMA against a constant all-ones B-fragment
//    (0x3C003C00): ol += P.1 — flash l recurrence rides the tensor pipe.
// ---------------------------------------------------------------------------
#define ASTR 72   // smem row stride (halves) = 144B -> conflict-free ldsm
#define ONES_H2 0x3C003C00u

__global__ __launch_bounds__(256, 2)
void attn_h(const __half* __restrict__ QKV, __half* __restrict__ O) {
    extern __shared__ __align__(16) __half smh[];
    __half* Qs = smh;                  // [128][ASTR]  q rows, d cols (pre-scaled)
    __half* Ks = Qs + 128 * ASTR;      // [64][ASTR]   key rows, d cols
    __half* Vs = Ks + 64 * ASTR;       // [64][ASTR]   key rows, d cols (natural)

    const int tid  = threadIdx.x;
    const int wid  = tid >> 5;
    const int lane = tid & 31;
    const int lrow = lane >> 2;
    const int lcol = lane & 3;
    const int wrow = wid * 16;

    const int qt = blockIdx.x;
    const int b  = blockIdx.y >> 4;
    const int h  = blockIdx.y & 15;

    const __half* Qb = QKV + ((size_t)b * SEQ + (size_t)qt * 128) * QSTR + h * HDIM;
    const __half* Kb = QKV + (size_t)b * SEQ * QSTR + EMBED     + h * HDIM;
    const __half* Vb = QKV + (size_t)b * SEQ * QSTR + 2 * EMBED + h * HDIM;

    const int sc8 = (tid & 7) * 8;

    // Stage Q tile, pre-scaled by 0.125*log2(e) (log2-domain logits)
    {
        const __half2 sc = __floats2half2_rn(0.18033688f, 0.18033688f);
        #pragma unroll
        for (int it = 0; it < 4; it++) {
            int f = tid + it * 256;
            int r = f >> 3;
            int c = (f & 7) * 8;
            uint4 v = *(const uint4*)(Qb + (size_t)r * QSTR + c);
            __half2* hp = (__half2*)&v;
            hp[0] = __hmul2(hp[0], sc);
            hp[1] = __hmul2(hp[1], sc);
            hp[2] = __hmul2(hp[2], sc);
            hp[3] = __hmul2(hp[3], sc);
            *(uint4*)&Qs[r * ASTR + c] = v;
        }
    }

    // ldmatrix base addresses
    uint32_t qs_addr = smem_u32(&Qs[(wrow + (lane & 15)) * ASTR + ((lane >> 4) << 3)]);
    uint32_t ks_addr[4], vs_addr[4];
    #pragma unroll
    for (int pr = 0; pr < 4; pr++) {
        ks_addr[pr] = smem_u32(&Ks[(pr * 16 + ((lane >> 4) << 3) + (lane & 7)) * ASTR + (lane & 8)]);
        vs_addr[pr] = smem_u32(&Vs[(lane & 15) * ASTR + pr * 16 + ((lane >> 4) << 3)]);
    }

    const int kr0 = tid >> 3, kr1 = (tid + 256) >> 3;
    uint4 kreg[2], vreg[2];
    auto pf_k = [&](int kt) {
        const __half* Kt = Kb + (size_t)kt * 64 * QSTR;
        kreg[0] = *(const uint4*)(Kt + (size_t)kr0 * QSTR + sc8);
        kreg[1] = *(const uint4*)(Kt + (size_t)kr1 * QSTR + sc8);
    };
    auto pf_v = [&](int kt) {
        const __half* Vp = Vb + (size_t)kt * 64 * QSTR;
        vreg[0] = *(const uint4*)(Vp + (size_t)kr0 * QSTR + sc8);
        vreg[1] = *(const uint4*)(Vp + (size_t)kr1 * QSTR + sc8);
    };

    float m_i[2];
    float oc[8][4];
    float ol[4];             // row-sum accumulator (all-ones MMA): l recurrence
    m_i[0] = m_i[1] = -INFINITY;
    ol[0] = ol[1] = ol[2] = ol[3] = 0.0f;
    #pragma unroll
    for (int nt = 0; nt < 8; nt++)
        #pragma unroll
        for (int j = 0; j < 4; j++) oc[nt][j] = 0.0f;

    const uint32_t ones_frag[2] = { ONES_H2, ONES_H2 };

    pf_k(0); pf_v(0);

    for (int kt = 0; kt < SEQ / 64; kt++) {
        __syncthreads();
        *(uint4*)&Ks[kr0 * ASTR + sc8] = kreg[0];
        *(uint4*)&Ks[kr1 * ASTR + sc8] = kreg[1];
        *(uint4*)&Vs[kr0 * ASTR + sc8] = vreg[0];
        *(uint4*)&Vs[kr1 * ASTR + sc8] = vreg[1];
        __syncthreads();

        const bool more = (kt + 1) < (SEQ / 64);
        if (more) pf_k(kt + 1);

        // ---- S = (Q*c) . K^T : log2-domain logits, 4 k16 steps ----
        float scv[8][4];
        #pragma unroll
        for (int nt = 0; nt < 8; nt++)
            #pragma unroll
            for (int j = 0; j < 4; j++) scv[nt][j] = 0.0f;

        #pragma unroll
        for (int ks = 0; ks < 4; ks++) {
            const uint32_t kb = ks * 32;
            uint32_t a[4];
            ldsm_x4(a, qs_addr + kb);
            #pragma unroll
            for (int pr = 0; pr < 4; pr++) {
                uint32_t bb[4];
                ldsm_x4(bb, ks_addr[pr] + kb);
                mma_f16(scv[2 * pr],     a, bb);
                mma_f16(scv[2 * pr + 1], a, bb + 2);
            }
        }

        // ---- online softmax in log2 domain; P via ex2.f16x2 straight into
        //      PV A-fragments ----
        uint32_t pa[4][4];
        #pragma unroll
        for (int rr = 0; rr < 2; rr++) {
            const int i0 = rr * 2;
            float tmax = -INFINITY;
            #pragma unroll
            for (int nt = 0; nt < 8; nt++)
                tmax = fmaxf(tmax, fmaxf(scv[nt][i0], scv[nt][i0 + 1]));
            tmax = fmaxf(tmax, __shfl_xor_sync(0xffffffffu, tmax, 1));
            tmax = fmaxf(tmax, __shfl_xor_sync(0xffffffffu, tmax, 2));
            float mnew  = fmaxf(m_i[rr], tmax);
            float alpha = exp2f(m_i[rr] - mnew);
            #pragma unroll
            for (int nt = 0; nt < 8; nt++) {
                __half2 dh = __floats2half2_rn(scv[nt][i0] - mnew, scv[nt][i0 + 1] - mnew);
                pa[nt >> 1][(nt & 1) * 2 + rr] = ex2_f16x2(*(uint32_t*)&dh);
                oc[nt][i0]     *= alpha;
                oc[nt][i0 + 1] *= alpha;
            }
            ol[i0]     *= alpha;
            ol[i0 + 1] *= alpha;
            m_i[rr] = mnew;
        }

        if (more) pf_v(kt + 1);

        // ---- l += P . 1 (constant ones B-fragment, tensor pipe) ----
        #pragma unroll
        for (int ks = 0; ks < 4; ks++)
            mma_f16(ol, pa[ks], ones_frag);

        // ---- O += P . V : A from registers, V frags via ldmatrix.trans ----
        #pragma unroll
        for (int ks = 0; ks < 4; ks++) {
            const uint32_t vko = (uint32_t)(ks * 16 * ASTR * 2);
            #pragma unroll
            for (int pr = 0; pr < 4; pr++) {
                uint32_t bb[4];
                ldsm_x4_t(bb, vs_addr[pr] + vko);
                mma_f16(oc[2 * pr],     pa[ks], bb);
                mma_f16(oc[2 * pr + 1], pa[ks], bb + 2);
            }
        }
    }

    // Epilogue: normalize by ol (row sums), convert fp16, write [B,T,D]
    __half* Ob = O + ((size_t)b * SEQ + (size_t)qt * 128) * EMBED + h * HDIM;
    #pragma unroll
    for (int rr = 0; rr < 2; rr++) {
        const float inv = 1.0f / ol[rr * 2];
        const int i0 = rr * 2;
        __half* orow = Ob + (size_t)(wrow + lrow + rr * 8) * EMBED + 2 * lcol;
        #pragma unroll
        for (int nt = 0; nt < 8; nt++)
            *(__half2*)(orow + nt * 8) =
                __floats2half2_rn(oc[nt][i0] * inv, oc[nt][i0 + 1] * inv);
    }
}

// ---------------------------------------------------------------------------
extern "C" void kernel_launch(void* const* d_in, const int* in_sizes, int n_in,
                              void* d_out, int out_size) {
    const float* x  = (const float*)d_in[0];
    const float* Wq = (const float*)d_in[1];
    const float* Wk = (const float*)d_in[2];
    const float* Wv = (const float*)d_in[3];
    const float* Wo = (const float*)d_in[4];
    float* out = (float*)d_out;

    __half *QKVh, *Oh, *Xh, *Wh;
    cudaGetSymbolAddress((void**)&QKVh, g_QKVh);
    cudaGetSymbolAddress((void**)&Oh, g_Oh);
    cudaGetSymbolAddress((void**)&Xh, g_Xh);
    cudaGetSymbolAddress((void**)&Wh, g_Wh);

    const size_t WSZ = (size_t)EMBED * EMBED;

    // Convert inputs to fp16
    {
        const int xn8 = (MTOT * EMBED) / 8;
        const int wn8 = (int)(WSZ / 8);
        f32_to_f16_kernel<<<xn8 / 256, 256>>>(Xh, x, xn8);
        f32_to_f16_w4<<<(4 * wn8) / 256, 256>>>(Wh, Wq, Wk, Wv, Wo, wn8);
    }

    // Fused QKV projection: [8192,1024] x [3072,1024]^T -> [8192,3072] fp16
    gemm_h<<<dim3(QSTR / 128, MTOT / 128), 256>>>(Xh, Wh, nullptr, QKVh, MTOT, QSTR, EMBED);

    const int attn_smem = (128 + 64 + 64) * ASTR * (int)sizeof(__half);  // 36864
    cudaFuncSetAttribute(attn_h, cudaFuncAttributeMaxDynamicSharedMemorySize, attn_smem);
    attn_h<<<dim3(SEQ / 128, BATCH * NHEADS), 256, attn_smem>>>(QKVh, Oh);

    // Final projection: fp32 output
    gemm_h<<<dim3(EMBED / 128, MTOT / 128), 256>>>(Oh, Wh + 3 * WSZ, out, nullptr, MTOT, EMBED, EMBED);
}